// round 15
// baseline (speedup 1.0000x reference)
#include <cuda_runtime.h>
#include <cuda_fp16.h>
#include <math.h>

#define EMB 768
#define SEQ 2048
#define BATCH 4
#define NHEAD 12
#define HDIM 64
#define FFDIM 3072
#define MROWS (BATCH*SEQ)   // 8192
#define NPROJ 3840
#define NCAT  4608
#define NQKV  2304
#define NGS   1536
#define NBH   (BATCH*NHEAD)

// ---------------- scratch (device globals) ----------------------------------
__device__ __half g_xnh  [MROWS*EMB];
__device__ __half g_qkvh [(size_t)MROWS*NQKV];
__device__ float  g_gs   [(size_t)MROWS*NGS];
__device__ __half g_ctxh [MROWS*EMB];
__device__ float  g_h    [MROWS*EMB];
__device__ __half g_hnh  [MROWS*EMB];
__device__ __half g_ff1h [(size_t)MROWS*FFDIM];
__device__ __half g_wcatT[(size_t)NCAT*EMB];
__device__ float  g_bcat [NCAT];
__device__ __half g_w1T  [(size_t)FFDIM*EMB];
__device__ __half g_w2T  [(size_t)EMB*FFDIM];

// ---------------- helpers ----------------------------------------------------
__device__ __forceinline__ unsigned smem_u32(const void* p) {
    unsigned a;
    asm("{ .reg .u64 t; cvta.to.shared.u64 t, %1; cvt.u32.u64 %0, t; }" : "=r"(a) : "l"(p));
    return a;
}
__device__ __forceinline__ void mma_f16(float (&d)[4], const unsigned (&a)[4],
                                        unsigned b0, unsigned b1) {
    asm volatile(
        "mma.sync.aligned.m16n8k16.row.col.f32.f16.f16.f32 "
        "{%0,%1,%2,%3},{%4,%5,%6,%7},{%8,%9},{%0,%1,%2,%3};\n"
        : "+f"(d[0]), "+f"(d[1]), "+f"(d[2]), "+f"(d[3])
        : "r"(a[0]), "r"(a[1]), "r"(a[2]), "r"(a[3]), "r"(b0), "r"(b1));
}
#define LDMX4(R, addr) \
    asm volatile("ldmatrix.sync.aligned.m8n8.x4.shared.b16 {%0,%1,%2,%3}, [%4];" \
        : "=r"((R)[0]), "=r"((R)[1]), "=r"((R)[2]), "=r"((R)[3]) : "r"(addr))
#define LDMX4T(R, addr) \
    asm volatile("ldmatrix.sync.aligned.m8n8.x4.trans.shared.b16 {%0,%1,%2,%3}, [%4];" \
        : "=r"((R)[0]), "=r"((R)[1]), "=r"((R)[2]), "=r"((R)[3]) : "r"(addr))
#define CPA(dst, src) asm volatile("cp.async.cg.shared.global [%0], [%1], 16;\n" :: "r"(dst), "l"(src))
#define CPCOMMIT()    asm volatile("cp.async.commit_group;\n" ::: "memory")
#define CPWAIT0()     asm volatile("cp.async.wait_group 0;\n" ::: "memory")
#define CPWAIT1()     asm volatile("cp.async.wait_group 1;\n" ::: "memory")

__device__ __forceinline__ void stcs_f2(float* p, float a, float b) {
    asm volatile("st.global.cs.v2.f32 [%0], {%1, %2};" :: "l"(p), "f"(a), "f"(b) : "memory");
}
__device__ __forceinline__ unsigned f22h(float lo, float hi) {
    unsigned u;
    asm("cvt.rn.f16x2.f32 %0, %1, %2;" : "=r"(u) : "f"(hi), "f"(lo));
    return u;
}
__device__ __forceinline__ float gelu_exact(float v) {
    return 0.5f * v * (1.0f + erff(v * 0.70710678118654752f));
}

// ---------------- weight prep ------------------------------------------------
__global__ __launch_bounds__(256) void prep_wcat_t(
    const float* __restrict__ wq, const float* __restrict__ wk,
    const float* __restrict__ wv, const float* __restrict__ wg,
    const float* __restrict__ ws, const float* __restrict__ wo,
    __half* __restrict__ dst)
{
    __shared__ float tile[32][33];
    int bx = blockIdx.x << 5;
    int by = blockIdx.y << 5;
    int tx = threadIdx.x & 31, ty = threadIdx.x >> 5;
    int sel = bx / 768, cc0 = bx - sel * 768;
    const float* w = (sel == 0) ? wq : (sel == 1) ? wk : (sel == 2) ? wv
                   : (sel == 3) ? wg : (sel == 4) ? ws : wo;
    float sc = (sel == 0) ? 0.125f : 1.0f;
    #pragma unroll
    for (int i = 0; i < 32; i += 8)
        tile[ty + i][tx] = w[(size_t)(by + ty + i) * 768 + cc0 + tx] * sc;
    __syncthreads();
    #pragma unroll
    for (int i = 0; i < 32; i += 8)
        dst[(size_t)(bx + ty + i) * 768 + by + tx] = __float2half_rn(tile[tx][ty + i]);
}

__global__ __launch_bounds__(256) void prep_bcat(
    const float* __restrict__ bq, const float* __restrict__ bk,
    const float* __restrict__ bv, const float* __restrict__ bg,
    const float* __restrict__ bs, const float* __restrict__ bo,
    float* __restrict__ bcat)
{
    int idx = blockIdx.x * 256 + threadIdx.x;
    if (idx >= NCAT) return;
    int sel = idx / 768, cc = idx - sel * 768;
    const float* bb = (sel == 0) ? bq : (sel == 1) ? bk : (sel == 2) ? bv
                    : (sel == 3) ? bg : (sel == 4) ? bs : bo;
    bcat[idx] = bb[cc] * ((sel == 0) ? 0.125f : 1.0f);
}

__global__ __launch_bounds__(256) void transpose_cvt(
    const float* __restrict__ src, __half* __restrict__ dst, int K, int N)
{
    __shared__ float tile[32][33];
    int bx = blockIdx.x << 5, by = blockIdx.y << 5;
    int tx = threadIdx.x & 31, ty = threadIdx.x >> 5;
    #pragma unroll
    for (int i = 0; i < 32; i += 8)
        tile[ty + i][tx] = src[(size_t)(by + ty + i) * N + bx + tx];
    __syncthreads();
    #pragma unroll
    for (int i = 0; i < 32; i += 8)
        dst[(size_t)(bx + ty + i) * K + by + tx] = __float2half_rn(tile[tx][ty + i]);
}

// ---------------- layernorm → half ------------------------------------------
__global__ __launch_bounds__(256) void ln_kernel(
    const float* __restrict__ x, const float* __restrict__ w,
    const float* __restrict__ b, __half* __restrict__ y)
{
    __shared__ float sh[8];
    int t = threadIdx.x;
    const float* xr = x + (size_t)blockIdx.x * EMB;
    float2 v01 = *(const float2*)(xr + 2 * t);
    float v2 = xr[512 + t];

    float s = v01.x + v01.y + v2;
    #pragma unroll
    for (int o = 16; o; o >>= 1) s += __shfl_xor_sync(~0u, s, o);
    if ((t & 31) == 0) sh[t >> 5] = s;
    __syncthreads();
    float mean = (sh[0]+sh[1]+sh[2]+sh[3]+sh[4]+sh[5]+sh[6]+sh[7]) * (1.0f/768.0f);
    __syncthreads();

    float d0 = v01.x - mean, d1 = v01.y - mean, d2 = v2 - mean;
    float q = d0*d0 + d1*d1 + d2*d2;
    #pragma unroll
    for (int o = 16; o; o >>= 1) q += __shfl_xor_sync(~0u, q, o);
    if ((t & 31) == 0) sh[t >> 5] = q;
    __syncthreads();
    float var = (sh[0]+sh[1]+sh[2]+sh[3]+sh[4]+sh[5]+sh[6]+sh[7]) * (1.0f/768.0f);
    float rstd = rsqrtf(var + 1e-5f);

    float2 w01 = *(const float2*)(w + 2 * t);
    float2 b01 = *(const float2*)(b + 2 * t);
    __half* yr = y + (size_t)blockIdx.x * EMB;
    *(__half2*)(yr + 2 * t) =
        __floats2half2_rn(d0 * rstd * w01.x + b01.x, d1 * rstd * w01.y + b01.y);
    yr[512 + t] = __float2half_rn(d2 * rstd * w[512 + t] + b[512 + t]);
}

// ---------------- fp16 GEMM 128x128x64, 4 warps, 3-stage, 2 CTA/SM ----------
// EPI: 2 bias+GELU->half; 4 split qkv/gs
#define G2_OP (128 * 72)
#define G2_STAGE (2 * G2_OP)
#define GEMM_SMEM (3 * G2_STAGE * 2)

template <int EPI>
__global__ __launch_bounds__(128, 2) void gemm_f16(
    const __half* __restrict__ A, const __half* __restrict__ Bt,
    const float* __restrict__ bias, const float* __restrict__ R,
    void* __restrict__ C0, void* __restrict__ C1, int M, int N, int K)
{
    extern __shared__ __half gsm[];
    int t = threadIdx.x, l = t & 31, warp = t >> 5;
    int wm = warp >> 1, wn = warp & 1;
    int g = l >> 2, r = l & 3;
    int bm0 = blockIdx.y * 128, bn0 = blockIdx.x * 128;
    int niter = K >> 6;

    int rowA = l & 15, colA8 = (l >> 4) << 3;
    int rowB = (l & 7) + ((l & 16) >> 1), colB8 = l & 8;
    int baseA = (wm * 64 + rowA) * 72 + colA8;
    int baseB = (wn * 64 + rowB) * 72 + colB8;

    float acc[4][8][4];
    #pragma unroll
    for (int i = 0; i < 4; i++)
        #pragma unroll
        for (int j = 0; j < 8; j++)
            #pragma unroll
            for (int q = 0; q < 4; q++) acc[i][j][q] = 0.0f;

    auto issue = [&](int it, int s) {
        int k0 = it << 6;
        unsigned sa = smem_u32(gsm + s * G2_STAGE);
        unsigned sb = sa + G2_OP * 2;
        #pragma unroll
        for (int u = 0; u < 8; u++) {
            int c = t + (u << 7);
            int row = c >> 3, cg = (c & 7) << 3;
            CPA(sa + (unsigned)((row * 72 + cg) << 1),
                A + (size_t)(bm0 + row) * K + k0 + cg);
        }
        #pragma unroll
        for (int u = 0; u < 8; u++) {
            int c = t + (u << 7);
            int row = c >> 3, cg = (c & 7) << 3;
            CPA(sb + (unsigned)((row * 72 + cg) << 1),
                Bt + (size_t)(bn0 + row) * K + k0 + cg);
        }
    };

    issue(0, 0); CPCOMMIT();
    if (niter > 1) issue(1, 1);
    CPCOMMIT();

    int st = 0;
    for (int it = 0; it < niter; ++it) {
        CPWAIT1();
        __syncthreads();
        int nx = st + 2; if (nx >= 3) nx -= 3;
        if (it + 2 < niter) issue(it + 2, nx);
        CPCOMMIT();

        unsigned sa = smem_u32(gsm + st * G2_STAGE);
        unsigned sb = sa + G2_OP * 2;
        #pragma unroll
        for (int ks = 0; ks < 4; ++ks) {
            unsigned Af[4][4], Bf[4][4];
            #pragma unroll
            for (int mf = 0; mf < 4; ++mf)
                LDMX4(Af[mf], sa + (unsigned)((baseA + mf * 1152 + ks * 16) << 1));
            #pragma unroll
            for (int nfp = 0; nfp < 4; ++nfp)
                LDMX4(Bf[nfp], sb + (unsigned)((baseB + nfp * 1152 + ks * 16) << 1));
            #pragma unroll
            for (int mf = 0; mf < 4; ++mf)
                #pragma unroll
                for (int nfp = 0; nfp < 4; ++nfp) {
                    mma_f16(acc[mf][2*nfp],   Af[mf], Bf[nfp][0], Bf[nfp][1]);
                    mma_f16(acc[mf][2*nfp+1], Af[mf], Bf[nfp][2], Bf[nfp][3]);
                }
        }
        if (++st == 3) st = 0;
    }

    #pragma unroll
    for (int mf = 0; mf < 4; ++mf) {
        #pragma unroll
        for (int nf = 0; nf < 8; ++nf) {
            int row = bm0 + wm * 64 + mf * 16 + g;
            int col = bn0 + wn * 64 + nf * 8 + (r << 1);
            float b0 = bias[col], b1 = bias[col + 1];
            float v0 = acc[mf][nf][0] + b0, v1 = acc[mf][nf][1] + b1;
            float v2 = acc[mf][nf][2] + b0, v3 = acc[mf][nf][3] + b1;
            if (EPI == 2) {
                __half* C = (__half*)C0;
                *(__half2*)(C + (size_t)row * N + col) =
                    __floats2half2_rn(gelu_exact(v0), gelu_exact(v1));
                *(__half2*)(C + (size_t)(row + 8) * N + col) =
                    __floats2half2_rn(gelu_exact(v2), gelu_exact(v3));
            } else {
                if (col < NQKV) {
                    __half* C = (__half*)C0;
                    *(__half2*)(C + (size_t)row * NQKV + col)       = __floats2half2_rn(v0, v1);
                    *(__half2*)(C + (size_t)(row + 8) * NQKV + col) = __floats2half2_rn(v2, v3);
                } else {
                    float* C = (float*)C1;
                    *(float2*)(C + (size_t)row * NGS + col - NQKV)       = make_float2(v0, v1);
                    *(float2*)(C + (size_t)(row + 8) * NGS + col - NQKV) = make_float2(v2, v3);
                }
            }
        }
    }
}

// ---------------- fp16 GEMM 64x128x64 (N=768 GEMMs) -------------------------
// EPI: 3 bias+R->fp32(stcs, final out); 5 bias + gated combine -> h (fp32)
#define G6_A (64 * 72)
#define G6_B (128 * 72)
#define G6_STAGE (G6_A + G6_B)
#define GEMM64_SMEM (3 * G6_STAGE * 2)

template <int EPI>
__global__ __launch_bounds__(128, 2) void gemm64_f16(
    const __half* __restrict__ A, const __half* __restrict__ Bt,
    const float* __restrict__ bias, const float* __restrict__ R,
    const float* __restrict__ X, const float* __restrict__ GS,
    float* __restrict__ C, int M, int N, int K)
{
    extern __shared__ __half gsm[];
    int t = threadIdx.x, l = t & 31, warp = t >> 5;
    int wm = warp >> 1, wn = warp & 1;
    int g = l >> 2, r = l & 3;
    int bm0 = blockIdx.y * 64, bn0 = blockIdx.x * 128;
    int niter = K >> 6;

    int rowA = l & 15, colA8 = (l >> 4) << 3;
    int rowB = (l & 7) + ((l & 16) >> 1), colB8 = l & 8;
    int baseA = (wm * 32 + rowA) * 72 + colA8;
    int baseB = (wn * 64 + rowB) * 72 + colB8;

    float acc[2][8][4];
    #pragma unroll
    for (int i = 0; i < 2; i++)
        #pragma unroll
        for (int j = 0; j < 8; j++)
            #pragma unroll
            for (int q = 0; q < 4; q++) acc[i][j][q] = 0.0f;

    auto issue = [&](int it, int s) {
        int k0 = it << 6;
        unsigned sa = smem_u32(gsm + s * G6_STAGE);
        unsigned sb = sa + G6_A * 2;
        #pragma unroll
        for (int u = 0; u < 4; u++) {
            int c = t + (u << 7);
            int row = c >> 3, cg = (c & 7) << 3;
            CPA(sa + (unsigned)((row * 72 + cg) << 1),
                A + (size_t)(bm0 + row) * K + k0 + cg);
        }
        #pragma unroll
        for (int u = 0; u < 8; u++) {
            int c = t + (u << 7);
            int row = c >> 3, cg = (c & 7) << 3;
            CPA(sb + (unsigned)((row * 72 + cg) << 1),
                Bt + (size_t)(bn0 + row) * K + k0 + cg);
        }
    };

    issue(0, 0); CPCOMMIT();
    if (niter > 1) issue(1, 1);
    CPCOMMIT();

    int st = 0;
    for (int it = 0; it < niter; ++it) {
        CPWAIT1();
        __syncthreads();
        int nx = st + 2; if (nx >= 3) nx -= 3;
        if (it + 2 < niter) issue(it + 2, nx);
        CPCOMMIT();

        unsigned sa = smem_u32(gsm + st * G6_STAGE);
        unsigned sb = sa + G6_A * 2;
        #pragma unroll
        for (int ks = 0; ks < 4; ++ks) {
            unsigned Af[2][4], Bf[4][4];
            #pragma unroll
            for (int mf = 0; mf < 2; ++mf)
                LDMX4(Af[mf], sa + (unsigned)((baseA + mf * 1152 + ks * 16) << 1));
            #pragma unroll
            for (int nfp = 0; nfp < 4; ++nfp)
                LDMX4(Bf[nfp], sb + (unsigned)((baseB + nfp * 1152 + ks * 16) << 1));
            #pragma unroll
            for (int mf = 0; mf < 2; ++mf)
                #pragma unroll
                for (int nfp = 0; nfp < 4; ++nfp) {
                    mma_f16(acc[mf][2*nfp],   Af[mf], Bf[nfp][0], Bf[nfp][1]);
                    mma_f16(acc[mf][2*nfp+1], Af[mf], Bf[nfp][2], Bf[nfp][3]);
                }
        }
        if (++st == 3) st = 0;
    }

    #pragma unroll
    for (int mf = 0; mf < 2; ++mf) {
        #pragma unroll
        for (int nf = 0; nf < 8; ++nf) {
            int row = bm0 + wm * 32 + mf * 16 + g;
            int col = bn0 + wn * 64 + nf * 8 + (r << 1);
            float b0 = bias[col], b1 = bias[col + 1];
            float v0 = acc[mf][nf][0] + b0, v1 = acc[mf][nf][1] + b1;
            float v2 = acc[mf][nf][2] + b0, v3 = acc[mf][nf][3] + b1;
            if (EPI == 3) {
                const float2 r0 = *(const float2*)(R + (size_t)row * N + col);
                const float2 r1 = *(const float2*)(R + (size_t)(row + 8) * N + col);
                stcs_f2(C + (size_t)row * N + col,       v0 + r0.x, v1 + r0.y);
                stcs_f2(C + (size_t)(row + 8) * N + col, v2 + r1.x, v3 + r1.y);
            } else { // EPI 5: h = x + sig(g)*v + (1-sig(g))*skip
                const float2 x0 = *(const float2*)(X + (size_t)row * 768 + col);
                const float2 x1 = *(const float2*)(X + (size_t)(row + 8) * 768 + col);
                const float2 g0 = *(const float2*)(GS + (size_t)row * NGS + col);
                const float2 g1 = *(const float2*)(GS + (size_t)(row + 8) * NGS + col);
                const float2 s0 = *(const float2*)(GS + (size_t)row * NGS + 768 + col);
                const float2 s1 = *(const float2*)(GS + (size_t)(row + 8) * NGS + 768 + col);
                float a0 = 1.0f / (1.0f + __expf(-g0.x));
                float a1 = 1.0f / (1.0f + __expf(-g0.y));
                float a2 = 1.0f / (1.0f + __expf(-g1.x));
                float a3 = 1.0f / (1.0f + __expf(-g1.y));
                *(float2*)(C + (size_t)row * N + col) = make_float2(
                    x0.x + a0 * v0 + (1.0f - a0) * s0.x,
                    x0.y + a1 * v1 + (1.0f - a1) * s0.y);
                *(float2*)(C + (size_t)(row + 8) * N + col) = make_float2(
                    x1.x + a2 * v2 + (1.0f - a2) * s1.x,
                    x1.y + a3 * v3 + (1.0f - a3) * s1.y);
            }
        }
    }
}

// ---------------- fused flash-style attention (fp16, 3-stage) ---------------
#define KSTG (64 * 72)
#define ATTN_SMEM ((128*72 + 6*KSTG) * 2)

__global__ __launch_bounds__(256, 2) void attn_fused(
    const __half* __restrict__ qkv, float* __restrict__ attw,
    __half* __restrict__ ctx)
{
    extern __shared__ __half smh[];
    __half* Qs = smh;
    __half* Ks = Qs + 128 * 72;   // 3 stages
    __half* Vs = Ks + 3 * KSTG;   // 3 stages

    int bh = blockIdx.y, b = bh / NHEAD, h = bh % NHEAD;
    const __half* Qp = qkv + (size_t)b * SEQ * NQKV + h * HDIM;
    const __half* Kp = Qp + 768;
    const __half* Vp = Qp + 1536;
    float* Wo = attw + (size_t)bh * SEQ * SEQ;
    __half* Cc = ctx + (size_t)b * SEQ * EMB + h * HDIM;

    int t = threadIdx.x, l = t & 31, warp = t >> 5;
    int g = l >> 2, r = l & 3;
    int wrow = warp * 16;
    int bm0 = blockIdx.x * 128;

    unsigned sq = smem_u32(Qs);

    int rowA = l & 15, colA8 = (l >> 4) << 3;
    int rowB = (l & 7) + ((l & 16) >> 1), colB8 = l & 8;
    int baseQA = (wrow + rowA) * 72 + colA8;
    int baseKB = rowB * 72 + colB8;
    int baseVB = rowA * 72 + colA8;

    auto issueK = [&](int it, int s) {
        unsigned sk = smem_u32(Ks + s * KSTG);
        #pragma unroll
        for (int u = 0; u < 2; u++) {
            int c = t + (u << 8);
            int row = c >> 3, cc8 = (c & 7) << 3;
            CPA(sk + (unsigned)((row * 72 + cc8) << 1),
                Kp + (size_t)(it * 64 + row) * NQKV + cc8);
        }
    };
    auto issueV = [&](int it, int s) {
        unsigned sv = smem_u32(Vs + s * KSTG);
        #pragma unroll
        for (int u = 0; u < 2; u++) {
            int c = t + (u << 8);
            int row = c >> 3, cc8 = (c & 7) << 3;
            CPA(sv + (unsigned)((row * 72 + cc8) << 1),
                Vp + (size_t)(it * 64 + row) * NQKV + cc8);
        }
    };

    // Q + K0 in group0, K1 in group1
    {
        #pragma unroll
        for (int u = 0; u < 4; u++) {
            int c = t + (u << 8);
            int row = c >> 3, cc8 = (c & 7) << 3;
            CPA(sq + (unsigned)((row * 72 + cc8) << 1),
                Qp + (size_t)(bm0 + row) * NQKV + cc8);
        }
    }
    issueK(0, 0); CPCOMMIT();
    issueK(1, 1); CPCOMMIT();
    CPWAIT1(); __syncthreads();

    unsigned QA[4][4];
    #pragma unroll
    for (int ks = 0; ks < 4; ++ks)
        LDMX4(QA[ks], sq + (unsigned)((baseQA + ks * 16) << 1));

    float mh[2] = {-1e30f, -1e30f};
    float lh[2] = {0.0f, 0.0f};

    // ---------------- pass 1: online stats (3-stage K ring) -----------------
    int st = 0;
    for (int it = 0; it < SEQ / 64; ++it) {
        CPWAIT1();
        __syncthreads();
        int nx = st + 2; if (nx >= 3) nx -= 3;
        if (it + 2 < SEQ / 64) issueK(it + 2, nx);
        CPCOMMIT();

        unsigned sk = smem_u32(Ks + st * KSTG);
        float acc[8][4];
        #pragma unroll
        for (int nf = 0; nf < 8; nf++)
            #pragma unroll
            for (int q = 0; q < 4; q++) acc[nf][q] = 0.0f;

        #pragma unroll
        for (int ks = 0; ks < 4; ks++) {
            #pragma unroll
            for (int nfp = 0; nfp < 4; nfp++) {
                unsigned Bq[4];
                LDMX4(Bq, sk + (unsigned)((baseKB + nfp * 1152 + ks * 16) << 1));
                mma_f16(acc[2*nfp],     QA[ks], Bq[0], Bq[1]);
                mma_f16(acc[2*nfp + 1], QA[ks], Bq[2], Bq[3]);
            }
        }

        #pragma unroll
        for (int half = 0; half < 2; half++) {
            float mb = -1e30f;
            #pragma unroll
            for (int nf = 0; nf < 8; nf++)
                mb = fmaxf(mb, fmaxf(acc[nf][2*half], acc[nf][2*half+1]));
            mb = fmaxf(mb, __shfl_xor_sync(~0u, mb, 1));
            mb = fmaxf(mb, __shfl_xor_sync(~0u, mb, 2));
            float mn = fmaxf(mh[half], mb);
            float ss = 0.0f;
            #pragma unroll
            for (int nf = 0; nf < 8; nf++)
                ss += __expf(acc[nf][2*half] - mn) + __expf(acc[nf][2*half+1] - mn);
            ss += __shfl_xor_sync(~0u, ss, 1);
            ss += __shfl_xor_sync(~0u, ss, 2);
            lh[half] = lh[half] * __expf(mh[half] - mn) + ss;
            mh[half] = mn;
        }
        if (++st == 3) st = 0;
    }

    float invl[2] = {1.0f / lh[0], 1.0f / lh[1]};

    float acco[8][4];
    #pragma unroll
    for (int nf = 0; nf < 8; nf++)
        #pragma unroll
        for (int q = 0; q < 4; q++) acco[nf][q] = 0.0f;

    CPWAIT0(); __syncthreads();
    issueK(0, 0); issueV(0, 0); CPCOMMIT();
    issueK(1, 1); issueV(1, 1); CPCOMMIT();

    // ---------------- pass 2: recompute, PV first, store last (3-stage) -----
    st = 0;
    for (int it = 0; it < SEQ / 64; ++it) {
        CPWAIT1();
        __syncthreads();
        int nx = st + 2; if (nx >= 3) nx -= 3;
        if (it + 2 < SEQ / 64) { issueK(it + 2, nx); issueV(it + 2, nx); }
        CPCOMMIT();

        unsigned sk = smem_u32(Ks + st * KSTG);
        unsigned sv = smem_u32(Vs + st * KSTG);

        float acc[8][4];
        #pragma unroll
        for (int nf = 0; nf < 8; nf++)
            #pragma unroll
            for (int q = 0; q < 4; q++) acc[nf][q] = 0.0f;

        #pragma unroll
        for (int ks = 0; ks < 4; ks++) {
            #pragma unroll
            for (int nfp = 0; nfp < 4; nfp++) {
                unsigned Bq[4];
                LDMX4(Bq, sk + (unsigned)((baseKB + nfp * 1152 + ks * 16) << 1));
                mma_f16(acc[2*nfp],     QA[ks], Bq[0], Bq[1]);
                mma_f16(acc[2*nfp + 1], QA[ks], Bq[2], Bq[3]);
            }
        }

        #pragma unroll
        for (int nf = 0; nf < 8; nf++) {
            acc[nf][0] = __expf(acc[nf][0] - mh[0]) * invl[0];
            acc[nf][1] = __expf(acc[nf][1] - mh[0]) * invl[0];
            acc[nf][2] = __expf(acc[nf][2] - mh[1]) * invl[1];
            acc[nf][3] = __expf(acc[nf][3] - mh[1]) * invl[1];
        }

        #pragma unroll
        for (int j = 0; j < 4; j++) {
            unsigned Aw[4];
            Aw[0] = f22h(acc[2*j][0],   acc[2*j][1]);
            Aw[1] = f22h(acc[2*j][2],   acc[2*j][3]);
            Aw[2] = f22h(acc[2*j+1][0], acc[2*j+1][1]);
            Aw[3] = f22h(acc[2*j+1][2], acc[2*j+1][3]);
            #pragma unroll
            for (int nfp = 0; nfp < 4; nfp++) {
                unsigned Bv[4];
                LDMX4T(Bv, sv + (unsigned)((baseVB + j * 1152 + nfp * 16) << 1));
                mma_f16(acco[2*nfp],     Aw, Bv[0], Bv[1]);
                mma_f16(acco[2*nfp + 1], Aw, Bv[2], Bv[3]);
            }
        }

        {
            size_t ro0 = (size_t)(bm0 + wrow + g) * SEQ + it * 64 + (r << 1);
            size_t ro1 = ro0 + (size_t)8 * SEQ;
            #pragma unroll
            for (int nf = 0; nf < 8; nf++) {
                stcs_f2(Wo + ro0 + nf * 8, acc[nf][0], acc[nf][1]);
                stcs_f2(Wo + ro1 + nf * 8, acc[nf][2], acc[nf][3]);
            }
        }
        if (++st == 3) st = 0;
    }

    #pragma unroll
    for (int nf = 0; nf < 8; nf++) {
        int col = nf * 8 + (r << 1);
        *(__half2*)(Cc + (size_t)(bm0 + wrow + g) * EMB + col) =
            __floats2half2_rn(acco[nf][0], acco[nf][1]);
        *(__half2*)(Cc + (size_t)(bm0 + wrow + 8 + g) * EMB + col) =
            __floats2half2_rn(acco[nf][2], acco[nf][3]);
    }
}

// ---------------- launcher --------------------------------------------------
extern "C" void kernel_launch(void* const* d_in, const int* in_sizes, int n_in,
                              void* d_out, int out_size)
{
    const float* x      = (const float*)d_in[0];
    const float* ln1_w  = (const float*)d_in[1];
    const float* ln1_b  = (const float*)d_in[2];
    const float* w_q    = (const float*)d_in[3];
    const float* w_k    = (const float*)d_in[4];
    const float* w_v    = (const float*)d_in[5];
    const float* w_o    = (const float*)d_in[6];
    const float* b_q    = (const float*)d_in[7];
    const float* b_k    = (const float*)d_in[8];
    const float* b_v    = (const float*)d_in[9];
    const float* b_o    = (const float*)d_in[10];
    const float* w_gate = (const float*)d_in[11];
    const float* b_gate = (const float*)d_in[12];
    const float* w_skip = (const float*)d_in[13];
    const float* b_skip = (const float*)d_in[14];
    const float* ln2_w  = (const float*)d_in[15];
    const float* ln2_b  = (const float*)d_in[16];
    const float* w1     = (const float*)d_in[17];
    const float* b1     = (const float*)d_in[18];
    const float* w2     = (const float*)d_in[19];
    const float* b2     = (const float*)d_in[20];

    float* out  = (float*)d_out;
    float* attw = out + (size_t)MROWS * EMB;

    __half *xnh, *qkvh, *ctxh, *hnh, *ff1h, *wcatT, *w1T, *w2T;
    float *gs, *hbuf, *bcat;
    cudaGetSymbolAddress((void**)&xnh,   g_xnh);
    cudaGetSymbolAddress((void**)&qkvh,  g_qkvh);
    cudaGetSymbolAddress((void**)&gs,    g_gs);
    cudaGetSymbolAddress((void**)&ctxh,  g_ctxh);
    cudaGetSymbolAddress((void**)&hbuf,  g_h);
    cudaGetSymbolAddress((void**)&hnh,   g_hnh);
    cudaGetSymbolAddress((void**)&ff1h,  g_ff1h);
    cudaGetSymbolAddress((void**)&wcatT, g_wcatT);
    cudaGetSymbolAddress((void**)&bcat,  g_bcat);
    cudaGetSymbolAddress((void**)&w1T,   g_w1T);
    cudaGetSymbolAddress((void**)&w2T,   g_w2T);

    cudaFuncSetAttribute(attn_fused,
                         cudaFuncAttributeMaxDynamicSharedMemorySize, ATTN_SMEM);
    cudaFuncSetAttribute(gemm_f16<2>,
                         cudaFuncAttributeMaxDynamicSharedMemorySize, GEMM_SMEM);
    cudaFuncSetAttribute(gemm_f16<4>,
                         cudaFuncAttributeMaxDynamicSharedMemorySize, GEMM_SMEM);
    cudaFuncSetAttribute(gemm64_f16<3>,
                         cudaFuncAttributeMaxDynamicSharedMemorySize, GEMM64_SMEM);
    cudaFuncSetAttribute(gemm64_f16<5>,
                         cudaFuncAttributeMaxDynamicSharedMemorySize, GEMM64_SMEM);

    prep_wcat_t<<<dim3(NCAT / 32, 768 / 32), 256>>>(
        w_q, w_k, w_v, w_gate, w_skip, w_o, wcatT);
    prep_bcat<<<(NCAT + 255) / 256, 256>>>(b_q, b_k, b_v, b_gate, b_skip, b_o, bcat);

    ln_kernel<<<MROWS, 256>>>(x, ln1_w, ln1_b, xnh);

    gemm_f16<4><<<dim3(NPROJ / 128, MROWS / 128), 128, GEMM_SMEM>>>(
        xnh, wcatT, bcat, nullptr, qkvh, gs, MROWS, NPROJ, EMB);

    attn_fused<<<dim3(SEQ / 128, NBH), 256, ATTN_SMEM>>>(qkvh, attw, ctxh);

    transpose_cvt<<<dim3(FFDIM / 32, 768 / 32), 256>>>(w1, w1T, 768, FFDIM);
    transpose_cvt<<<dim3(768 / 32, FFDIM / 32), 256>>>(w2, w2T, FFDIM, 768);

    // output projection with fused gated combine -> h
    gemm64_f16<5><<<dim3(EMB / 128, MROWS / 64), 128, GEMM64_SMEM>>>(
        ctxh, wcatT + (size_t)NPROJ * 768, bcat + NPROJ, nullptr,
        x, gs, hbuf, MROWS, EMB, EMB);

    // LN2
    ln_kernel<<<MROWS, 256>>>(hbuf, ln2_w, ln2_b, hnh);

    gemm_f16<2><<<dim3(FFDIM / 128, MROWS / 128), 128, GEMM_SMEM>>>(
        hnh, w1T, b1, nullptr, ff1h, nullptr, MROWS, FFDIM, EMB);
    gemm64_f16<3><<<dim3(EMB / 128, MROWS / 64), 128, GEMM64_SMEM>>>(
        ff1h, w2T, b2, hbuf, nullptr, nullptr, out, MROWS, EMB, FFDIM);
}

// round 16
// speedup vs baseline: 1.0170x; 1.0170x over previous
#include <cuda_runtime.h>
#include <cuda_fp16.h>
#include <math.h>

#define EMB 768
#define SEQ 2048
#define BATCH 4
#define NHEAD 12
#define HDIM 64
#define FFDIM 3072
#define MROWS (BATCH*SEQ)   // 8192
#define NPROJ 3840
#define NCAT  4608
#define NQKV  2304
#define NGS   1536
#define NBH   (BATCH*NHEAD)

// ---------------- scratch (device globals) ----------------------------------
__device__ __half g_xnh  [MROWS*EMB];
__device__ __half g_qkvh [(size_t)MROWS*NQKV];
__device__ float  g_gs   [(size_t)MROWS*NGS];
__device__ __half g_ctxh [MROWS*EMB];
__device__ float  g_h    [MROWS*EMB];
__device__ __half g_hnh  [MROWS*EMB];
__device__ __half g_ff1h [(size_t)MROWS*FFDIM];
__device__ __half g_wcatT[(size_t)NCAT*EMB];
__device__ float  g_bcat [NCAT];
__device__ __half g_w1T  [(size_t)FFDIM*EMB];
__device__ __half g_w2T  [(size_t)EMB*FFDIM];

// ---------------- helpers ----------------------------------------------------
__device__ __forceinline__ unsigned smem_u32(const void* p) {
    unsigned a;
    asm("{ .reg .u64 t; cvta.to.shared.u64 t, %1; cvt.u32.u64 %0, t; }" : "=r"(a) : "l"(p));
    return a;
}
__device__ __forceinline__ void mma_f16(float (&d)[4], const unsigned (&a)[4],
                                        unsigned b0, unsigned b1) {
    asm volatile(
        "mma.sync.aligned.m16n8k16.row.col.f32.f16.f16.f32 "
        "{%0,%1,%2,%3},{%4,%5,%6,%7},{%8,%9},{%0,%1,%2,%3};\n"
        : "+f"(d[0]), "+f"(d[1]), "+f"(d[2]), "+f"(d[3])
        : "r"(a[0]), "r"(a[1]), "r"(a[2]), "r"(a[3]), "r"(b0), "r"(b1));
}
#define LDMX4(R, addr) \
    asm volatile("ldmatrix.sync.aligned.m8n8.x4.shared.b16 {%0,%1,%2,%3}, [%4];" \
        : "=r"((R)[0]), "=r"((R)[1]), "=r"((R)[2]), "=r"((R)[3]) : "r"(addr))
#define LDMX4T(R, addr) \
    asm volatile("ldmatrix.sync.aligned.m8n8.x4.trans.shared.b16 {%0,%1,%2,%3}, [%4];" \
        : "=r"((R)[0]), "=r"((R)[1]), "=r"((R)[2]), "=r"((R)[3]) : "r"(addr))
#define CPA(dst, src) asm volatile("cp.async.cg.shared.global [%0], [%1], 16;\n" :: "r"(dst), "l"(src))
#define CPCOMMIT()    asm volatile("cp.async.commit_group;\n" ::: "memory")
#define CPWAIT0()     asm volatile("cp.async.wait_group 0;\n" ::: "memory")
#define CPWAIT1()     asm volatile("cp.async.wait_group 1;\n" ::: "memory")

__device__ __forceinline__ void stcs_f2(float* p, float a, float b) {
    asm volatile("st.global.cs.v2.f32 [%0], {%1, %2};" :: "l"(p), "f"(a), "f"(b) : "memory");
}
__device__ __forceinline__ unsigned f22h(float lo, float hi) {
    unsigned u;
    asm("cvt.rn.f16x2.f32 %0, %1, %2;" : "=r"(u) : "f"(hi), "f"(lo));
    return u;
}
__device__ __forceinline__ float gelu_exact(float v) {
    return 0.5f * v * (1.0f + erff(v * 0.70710678118654752f));
}

// ---------------- weight prep ------------------------------------------------
__global__ __launch_bounds__(256) void prep_wcat_t(
    const float* __restrict__ wq, const float* __restrict__ wk,
    const float* __restrict__ wv, const float* __restrict__ wg,
    const float* __restrict__ ws, const float* __restrict__ wo,
    __half* __restrict__ dst)
{
    __shared__ float tile[32][33];
    int bx = blockIdx.x << 5;
    int by = blockIdx.y << 5;
    int tx = threadIdx.x & 31, ty = threadIdx.x >> 5;
    int sel = bx / 768, cc0 = bx - sel * 768;
    const float* w = (sel == 0) ? wq : (sel == 1) ? wk : (sel == 2) ? wv
                   : (sel == 3) ? wg : (sel == 4) ? ws : wo;
    float sc = (sel == 0) ? 0.125f : 1.0f;
    #pragma unroll
    for (int i = 0; i < 32; i += 8)
        tile[ty + i][tx] = w[(size_t)(by + ty + i) * 768 + cc0 + tx] * sc;
    __syncthreads();
    #pragma unroll
    for (int i = 0; i < 32; i += 8)
        dst[(size_t)(bx + ty + i) * 768 + by + tx] = __float2half_rn(tile[tx][ty + i]);
}

__global__ __launch_bounds__(256) void prep_bcat(
    const float* __restrict__ bq, const float* __restrict__ bk,
    const float* __restrict__ bv, const float* __restrict__ bg,
    const float* __restrict__ bs, const float* __restrict__ bo,
    float* __restrict__ bcat)
{
    int idx = blockIdx.x * 256 + threadIdx.x;
    if (idx >= NCAT) return;
    int sel = idx / 768, cc = idx - sel * 768;
    const float* bb = (sel == 0) ? bq : (sel == 1) ? bk : (sel == 2) ? bv
                    : (sel == 3) ? bg : (sel == 4) ? bs : bo;
    bcat[idx] = bb[cc] * ((sel == 0) ? 0.125f : 1.0f);
}

__global__ __launch_bounds__(256) void transpose_cvt(
    const float* __restrict__ src, __half* __restrict__ dst, int K, int N)
{
    __shared__ float tile[32][33];
    int bx = blockIdx.x << 5, by = blockIdx.y << 5;
    int tx = threadIdx.x & 31, ty = threadIdx.x >> 5;
    #pragma unroll
    for (int i = 0; i < 32; i += 8)
        tile[ty + i][tx] = src[(size_t)(by + ty + i) * N + bx + tx];
    __syncthreads();
    #pragma unroll
    for (int i = 0; i < 32; i += 8)
        dst[(size_t)(bx + ty + i) * K + by + tx] = __float2half_rn(tile[tx][ty + i]);
}

// ---------------- layernorm → half ------------------------------------------
__global__ __launch_bounds__(256) void ln_kernel(
    const float* __restrict__ x, const float* __restrict__ w,
    const float* __restrict__ b, __half* __restrict__ y)
{
    __shared__ float sh[8];
    int t = threadIdx.x;
    const float* xr = x + (size_t)blockIdx.x * EMB;
    float2 v01 = *(const float2*)(xr + 2 * t);
    float v2 = xr[512 + t];

    float s = v01.x + v01.y + v2;
    #pragma unroll
    for (int o = 16; o; o >>= 1) s += __shfl_xor_sync(~0u, s, o);
    if ((t & 31) == 0) sh[t >> 5] = s;
    __syncthreads();
    float mean = (sh[0]+sh[1]+sh[2]+sh[3]+sh[4]+sh[5]+sh[6]+sh[7]) * (1.0f/768.0f);
    __syncthreads();

    float d0 = v01.x - mean, d1 = v01.y - mean, d2 = v2 - mean;
    float q = d0*d0 + d1*d1 + d2*d2;
    #pragma unroll
    for (int o = 16; o; o >>= 1) q += __shfl_xor_sync(~0u, q, o);
    if ((t & 31) == 0) sh[t >> 5] = q;
    __syncthreads();
    float var = (sh[0]+sh[1]+sh[2]+sh[3]+sh[4]+sh[5]+sh[6]+sh[7]) * (1.0f/768.0f);
    float rstd = rsqrtf(var + 1e-5f);

    float2 w01 = *(const float2*)(w + 2 * t);
    float2 b01 = *(const float2*)(b + 2 * t);
    __half* yr = y + (size_t)blockIdx.x * EMB;
    *(__half2*)(yr + 2 * t) =
        __floats2half2_rn(d0 * rstd * w01.x + b01.x, d1 * rstd * w01.y + b01.y);
    yr[512 + t] = __float2half_rn(d2 * rstd * w[512 + t] + b[512 + t]);
}

// ---------------- fp16 GEMM 128x128x64, 4 warps, 3-stage, 2 CTA/SM ----------
// EPI: 2 bias+GELU->half; 4 split qkv/gs
#define G2_OP (128 * 72)
#define G2_STAGE (2 * G2_OP)
#define GEMM_SMEM (3 * G2_STAGE * 2)

template <int EPI>
__global__ __launch_bounds__(128, 2) void gemm_f16(
    const __half* __restrict__ A, const __half* __restrict__ Bt,
    const float* __restrict__ bias, const float* __restrict__ R,
    void* __restrict__ C0, void* __restrict__ C1, int M, int N, int K)
{
    extern __shared__ __half gsm[];
    int t = threadIdx.x, l = t & 31, warp = t >> 5;
    int wm = warp >> 1, wn = warp & 1;
    int g = l >> 2, r = l & 3;
    int bm0 = blockIdx.y * 128, bn0 = blockIdx.x * 128;
    int niter = K >> 6;

    int rowA = l & 15, colA8 = (l >> 4) << 3;
    int rowB = (l & 7) + ((l & 16) >> 1), colB8 = l & 8;
    int baseA = (wm * 64 + rowA) * 72 + colA8;
    int baseB = (wn * 64 + rowB) * 72 + colB8;

    float acc[4][8][4];
    #pragma unroll
    for (int i = 0; i < 4; i++)
        #pragma unroll
        for (int j = 0; j < 8; j++)
            #pragma unroll
            for (int q = 0; q < 4; q++) acc[i][j][q] = 0.0f;

    auto issue = [&](int it, int s) {
        int k0 = it << 6;
        unsigned sa = smem_u32(gsm + s * G2_STAGE);
        unsigned sb = sa + G2_OP * 2;
        #pragma unroll
        for (int u = 0; u < 8; u++) {
            int c = t + (u << 7);
            int row = c >> 3, cg = (c & 7) << 3;
            CPA(sa + (unsigned)((row * 72 + cg) << 1),
                A + (size_t)(bm0 + row) * K + k0 + cg);
        }
        #pragma unroll
        for (int u = 0; u < 8; u++) {
            int c = t + (u << 7);
            int row = c >> 3, cg = (c & 7) << 3;
            CPA(sb + (unsigned)((row * 72 + cg) << 1),
                Bt + (size_t)(bn0 + row) * K + k0 + cg);
        }
    };

    issue(0, 0); CPCOMMIT();
    if (niter > 1) issue(1, 1);
    CPCOMMIT();

    int st = 0;
    for (int it = 0; it < niter; ++it) {
        CPWAIT1();
        __syncthreads();
        int nx = st + 2; if (nx >= 3) nx -= 3;
        if (it + 2 < niter) issue(it + 2, nx);
        CPCOMMIT();

        unsigned sa = smem_u32(gsm + st * G2_STAGE);
        unsigned sb = sa + G2_OP * 2;
        #pragma unroll
        for (int ks = 0; ks < 4; ++ks) {
            unsigned Af[4][4], Bf[4][4];
            #pragma unroll
            for (int mf = 0; mf < 4; ++mf)
                LDMX4(Af[mf], sa + (unsigned)((baseA + mf * 1152 + ks * 16) << 1));
            #pragma unroll
            for (int nfp = 0; nfp < 4; ++nfp)
                LDMX4(Bf[nfp], sb + (unsigned)((baseB + nfp * 1152 + ks * 16) << 1));
            #pragma unroll
            for (int mf = 0; mf < 4; ++mf)
                #pragma unroll
                for (int nfp = 0; nfp < 4; ++nfp) {
                    mma_f16(acc[mf][2*nfp],   Af[mf], Bf[nfp][0], Bf[nfp][1]);
                    mma_f16(acc[mf][2*nfp+1], Af[mf], Bf[nfp][2], Bf[nfp][3]);
                }
        }
        if (++st == 3) st = 0;
    }

    #pragma unroll
    for (int mf = 0; mf < 4; ++mf) {
        #pragma unroll
        for (int nf = 0; nf < 8; ++nf) {
            int row = bm0 + wm * 64 + mf * 16 + g;
            int col = bn0 + wn * 64 + nf * 8 + (r << 1);
            float b0 = bias[col], b1 = bias[col + 1];
            float v0 = acc[mf][nf][0] + b0, v1 = acc[mf][nf][1] + b1;
            float v2 = acc[mf][nf][2] + b0, v3 = acc[mf][nf][3] + b1;
            if (EPI == 2) {
                __half* C = (__half*)C0;
                *(__half2*)(C + (size_t)row * N + col) =
                    __floats2half2_rn(gelu_exact(v0), gelu_exact(v1));
                *(__half2*)(C + (size_t)(row + 8) * N + col) =
                    __floats2half2_rn(gelu_exact(v2), gelu_exact(v3));
            } else {
                if (col < NQKV) {
                    __half* C = (__half*)C0;
                    *(__half2*)(C + (size_t)row * NQKV + col)       = __floats2half2_rn(v0, v1);
                    *(__half2*)(C + (size_t)(row + 8) * NQKV + col) = __floats2half2_rn(v2, v3);
                } else {
                    float* C = (float*)C1;
                    *(float2*)(C + (size_t)row * NGS + col - NQKV)       = make_float2(v0, v1);
                    *(float2*)(C + (size_t)(row + 8) * NGS + col - NQKV) = make_float2(v2, v3);
                }
            }
        }
    }
}

// ---------------- fp16 GEMM 64x128x64 (N=768 GEMMs) -------------------------
// EPI: 3 bias+R->fp32(stcs, final out); 5 bias + gated combine -> h (fp32)
#define G6_A (64 * 72)
#define G6_B (128 * 72)
#define G6_STAGE (G6_A + G6_B)
#define GEMM64_SMEM (3 * G6_STAGE * 2)

template <int EPI>
__global__ __launch_bounds__(128, 2) void gemm64_f16(
    const __half* __restrict__ A, const __half* __restrict__ Bt,
    const float* __restrict__ bias, const float* __restrict__ R,
    const float* __restrict__ X, const float* __restrict__ GS,
    float* __restrict__ C, int M, int N, int K)
{
    extern __shared__ __half gsm[];
    int t = threadIdx.x, l = t & 31, warp = t >> 5;
    int wm = warp >> 1, wn = warp & 1;
    int g = l >> 2, r = l & 3;
    int bm0 = blockIdx.y * 64, bn0 = blockIdx.x * 128;
    int niter = K >> 6;

    int rowA = l & 15, colA8 = (l >> 4) << 3;
    int rowB = (l & 7) + ((l & 16) >> 1), colB8 = l & 8;
    int baseA = (wm * 32 + rowA) * 72 + colA8;
    int baseB = (wn * 64 + rowB) * 72 + colB8;

    float acc[2][8][4];
    #pragma unroll
    for (int i = 0; i < 2; i++)
        #pragma unroll
        for (int j = 0; j < 8; j++)
            #pragma unroll
            for (int q = 0; q < 4; q++) acc[i][j][q] = 0.0f;

    auto issue = [&](int it, int s) {
        int k0 = it << 6;
        unsigned sa = smem_u32(gsm + s * G6_STAGE);
        unsigned sb = sa + G6_A * 2;
        #pragma unroll
        for (int u = 0; u < 4; u++) {
            int c = t + (u << 7);
            int row = c >> 3, cg = (c & 7) << 3;
            CPA(sa + (unsigned)((row * 72 + cg) << 1),
                A + (size_t)(bm0 + row) * K + k0 + cg);
        }
        #pragma unroll
        for (int u = 0; u < 8; u++) {
            int c = t + (u << 7);
            int row = c >> 3, cg = (c & 7) << 3;
            CPA(sb + (unsigned)((row * 72 + cg) << 1),
                Bt + (size_t)(bn0 + row) * K + k0 + cg);
        }
    };

    issue(0, 0); CPCOMMIT();
    if (niter > 1) issue(1, 1);
    CPCOMMIT();

    int st = 0;
    for (int it = 0; it < niter; ++it) {
        CPWAIT1();
        __syncthreads();
        int nx = st + 2; if (nx >= 3) nx -= 3;
        if (it + 2 < niter) issue(it + 2, nx);
        CPCOMMIT();

        unsigned sa = smem_u32(gsm + st * G6_STAGE);
        unsigned sb = sa + G6_A * 2;
        #pragma unroll
        for (int ks = 0; ks < 4; ++ks) {
            unsigned Af[2][4], Bf[4][4];
            #pragma unroll
            for (int mf = 0; mf < 2; ++mf)
                LDMX4(Af[mf], sa + (unsigned)((baseA + mf * 1152 + ks * 16) << 1));
            #pragma unroll
            for (int nfp = 0; nfp < 4; ++nfp)
                LDMX4(Bf[nfp], sb + (unsigned)((baseB + nfp * 1152 + ks * 16) << 1));
            #pragma unroll
            for (int mf = 0; mf < 2; ++mf)
                #pragma unroll
                for (int nfp = 0; nfp < 4; ++nfp) {
                    mma_f16(acc[mf][2*nfp],   Af[mf], Bf[nfp][0], Bf[nfp][1]);
                    mma_f16(acc[mf][2*nfp+1], Af[mf], Bf[nfp][2], Bf[nfp][3]);
                }
        }
        if (++st == 3) st = 0;
    }

    #pragma unroll
    for (int mf = 0; mf < 2; ++mf) {
        #pragma unroll
        for (int nf = 0; nf < 8; ++nf) {
            int row = bm0 + wm * 32 + mf * 16 + g;
            int col = bn0 + wn * 64 + nf * 8 + (r << 1);
            float b0 = bias[col], b1 = bias[col + 1];
            float v0 = acc[mf][nf][0] + b0, v1 = acc[mf][nf][1] + b1;
            float v2 = acc[mf][nf][2] + b0, v3 = acc[mf][nf][3] + b1;
            if (EPI == 3) {
                const float2 r0 = *(const float2*)(R + (size_t)row * N + col);
                const float2 r1 = *(const float2*)(R + (size_t)(row + 8) * N + col);
                stcs_f2(C + (size_t)row * N + col,       v0 + r0.x, v1 + r0.y);
                stcs_f2(C + (size_t)(row + 8) * N + col, v2 + r1.x, v3 + r1.y);
            } else { // EPI 5: h = x + sig(g)*v + (1-sig(g))*skip
                const float2 x0 = *(const float2*)(X + (size_t)row * 768 + col);
                const float2 x1 = *(const float2*)(X + (size_t)(row + 8) * 768 + col);
                const float2 g0 = *(const float2*)(GS + (size_t)row * NGS + col);
                const float2 g1 = *(const float2*)(GS + (size_t)(row + 8) * NGS + col);
                const float2 s0 = *(const float2*)(GS + (size_t)row * NGS + 768 + col);
                const float2 s1 = *(const float2*)(GS + (size_t)(row + 8) * NGS + 768 + col);
                float a0 = 1.0f / (1.0f + __expf(-g0.x));
                float a1 = 1.0f / (1.0f + __expf(-g0.y));
                float a2 = 1.0f / (1.0f + __expf(-g1.x));
                float a3 = 1.0f / (1.0f + __expf(-g1.y));
                *(float2*)(C + (size_t)row * N + col) = make_float2(
                    x0.x + a0 * v0 + (1.0f - a0) * s0.x,
                    x0.y + a1 * v1 + (1.0f - a1) * s0.y);
                *(float2*)(C + (size_t)(row + 8) * N + col) = make_float2(
                    x1.x + a2 * v2 + (1.0f - a2) * s1.x,
                    x1.y + a3 * v3 + (1.0f - a3) * s1.y);
            }
        }
    }
}

// ---------------- fused flash-style attention (fp16, 2-stage, R14) ----------
#define ATTN_SMEM ((128*72 + 4*64*72) * 2)

__global__ __launch_bounds__(256, 2) void attn_fused(
    const __half* __restrict__ qkv, float* __restrict__ attw,
    __half* __restrict__ ctx)
{
    extern __shared__ __half smh[];
    __half* Qs  = smh;
    __half* Ks0 = Qs  + 128 * 72;
    __half* Ks1 = Ks0 + 64 * 72;
    __half* Vs0 = Ks1 + 64 * 72;
    __half* Vs1 = Vs0 + 64 * 72;

    int bh = blockIdx.y, b = bh / NHEAD, h = bh % NHEAD;
    const __half* Qp = qkv + (size_t)b * SEQ * NQKV + h * HDIM;
    const __half* Kp = Qp + 768;
    const __half* Vp = Qp + 1536;
    float* Wo = attw + (size_t)bh * SEQ * SEQ;
    __half* Cc = ctx + (size_t)b * SEQ * EMB + h * HDIM;

    int t = threadIdx.x, l = t & 31, warp = t >> 5;
    int g = l >> 2, r = l & 3;
    int wrow = warp * 16;
    int bm0 = blockIdx.x * 128;

    unsigned sq  = smem_u32(Qs);
    unsigned sk0 = smem_u32(Ks0), sk1 = smem_u32(Ks1);
    unsigned sv0 = smem_u32(Vs0), sv1 = smem_u32(Vs1);

    int rowA = l & 15, colA8 = (l >> 4) << 3;
    int rowB = (l & 7) + ((l & 16) >> 1), colB8 = l & 8;
    int baseQA = (wrow + rowA) * 72 + colA8;
    int baseKB = rowB * 72 + colB8;
    int baseVB = rowA * 72 + colA8;

    auto issueK = [&](int it, int s) {
        unsigned sk = s ? sk1 : sk0;
        #pragma unroll
        for (int u = 0; u < 2; u++) {
            int c = t + (u << 8);
            int row = c >> 3, cc8 = (c & 7) << 3;
            CPA(sk + (unsigned)((row * 72 + cc8) << 1),
                Kp + (size_t)(it * 64 + row) * NQKV + cc8);
        }
    };
    auto issueV = [&](int it, int s) {
        unsigned sv = s ? sv1 : sv0;
        #pragma unroll
        for (int u = 0; u < 2; u++) {
            int c = t + (u << 8);
            int row = c >> 3, cc8 = (c & 7) << 3;
            CPA(sv + (unsigned)((row * 72 + cc8) << 1),
                Vp + (size_t)(it * 64 + row) * NQKV + cc8);
        }
    };

    {
        #pragma unroll
        for (int u = 0; u < 4; u++) {
            int c = t + (u << 8);
            int row = c >> 3, cc8 = (c & 7) << 3;
            CPA(sq + (unsigned)((row * 72 + cc8) << 1),
                Qp + (size_t)(bm0 + row) * NQKV + cc8);
        }
    }
    issueK(0, 0); CPCOMMIT();
    CPWAIT0(); __syncthreads();

    unsigned QA[4][4];
    #pragma unroll
    for (int ks = 0; ks < 4; ++ks)
        LDMX4(QA[ks], sq + (unsigned)((baseQA + ks * 16) << 1));

    float mh[2] = {-1e30f, -1e30f};
    float lh[2] = {0.0f, 0.0f};

    // ---------------- pass 1: online stats ----------------
    for (int it = 0; it < SEQ / 64; ++it) {
        if (it + 1 < SEQ / 64) { issueK(it + 1, (it + 1) & 1); CPCOMMIT(); }
        unsigned sk = (it & 1) ? sk1 : sk0;

        float acc[8][4];
        #pragma unroll
        for (int nf = 0; nf < 8; nf++)
            #pragma unroll
            for (int q = 0; q < 4; q++) acc[nf][q] = 0.0f;

        #pragma unroll
        for (int ks = 0; ks < 4; ks++) {
            #pragma unroll
            for (int nfp = 0; nfp < 4; nfp++) {
                unsigned Bq[4];
                LDMX4(Bq, sk + (unsigned)((baseKB + nfp * 1152 + ks * 16) << 1));
                mma_f16(acc[2*nfp],     QA[ks], Bq[0], Bq[1]);
                mma_f16(acc[2*nfp + 1], QA[ks], Bq[2], Bq[3]);
            }
        }

        #pragma unroll
        for (int half = 0; half < 2; half++) {
            float mb = -1e30f;
            #pragma unroll
            for (int nf = 0; nf < 8; nf++)
                mb = fmaxf(mb, fmaxf(acc[nf][2*half], acc[nf][2*half+1]));
            mb = fmaxf(mb, __shfl_xor_sync(~0u, mb, 1));
            mb = fmaxf(mb, __shfl_xor_sync(~0u, mb, 2));
            float mn = fmaxf(mh[half], mb);
            float ss = 0.0f;
            #pragma unroll
            for (int nf = 0; nf < 8; nf++)
                ss += __expf(acc[nf][2*half] - mn) + __expf(acc[nf][2*half+1] - mn);
            ss += __shfl_xor_sync(~0u, ss, 1);
            ss += __shfl_xor_sync(~0u, ss, 2);
            lh[half] = lh[half] * __expf(mh[half] - mn) + ss;
            mh[half] = mn;
        }
        if (it + 1 < SEQ / 64) { CPWAIT0(); __syncthreads(); }
    }

    float invl[2] = {1.0f / lh[0], 1.0f / lh[1]};

    float acco[8][4];
    #pragma unroll
    for (int nf = 0; nf < 8; nf++)
        #pragma unroll
        for (int q = 0; q < 4; q++) acco[nf][q] = 0.0f;

    __syncthreads();
    issueK(0, 0); issueV(0, 0); CPCOMMIT();
    CPWAIT0(); __syncthreads();

    // ---------------- pass 2: recompute, PV first, store last ---------------
    for (int it = 0; it < SEQ / 64; ++it) {
        if (it + 1 < SEQ / 64) {
            issueK(it + 1, (it + 1) & 1); issueV(it + 1, (it + 1) & 1); CPCOMMIT();
        }
        unsigned sk = (it & 1) ? sk1 : sk0;
        unsigned sv = (it & 1) ? sv1 : sv0;

        float acc[8][4];
        #pragma unroll
        for (int nf = 0; nf < 8; nf++)
            #pragma unroll
            for (int q = 0; q < 4; q++) acc[nf][q] = 0.0f;

        #pragma unroll
        for (int ks = 0; ks < 4; ks++) {
            #pragma unroll
            for (int nfp = 0; nfp < 4; nfp++) {
                unsigned Bq[4];
                LDMX4(Bq, sk + (unsigned)((baseKB + nfp * 1152 + ks * 16) << 1));
                mma_f16(acc[2*nfp],     QA[ks], Bq[0], Bq[1]);
                mma_f16(acc[2*nfp + 1], QA[ks], Bq[2], Bq[3]);
            }
        }

        #pragma unroll
        for (int nf = 0; nf < 8; nf++) {
            acc[nf][0] = __expf(acc[nf][0] - mh[0]) * invl[0];
            acc[nf][1] = __expf(acc[nf][1] - mh[0]) * invl[0];
            acc[nf][2] = __expf(acc[nf][2] - mh[1]) * invl[1];
            acc[nf][3] = __expf(acc[nf][3] - mh[1]) * invl[1];
        }

        #pragma unroll
        for (int j = 0; j < 4; j++) {
            unsigned Aw[4];
            Aw[0] = f22h(acc[2*j][0],   acc[2*j][1]);
            Aw[1] = f22h(acc[2*j][2],   acc[2*j][3]);
            Aw[2] = f22h(acc[2*j+1][0], acc[2*j+1][1]);
            Aw[3] = f22h(acc[2*j+1][2], acc[2*j+1][3]);
            #pragma unroll
            for (int nfp = 0; nfp < 4; nfp++) {
                unsigned Bv[4];
                LDMX4T(Bv, sv + (unsigned)((baseVB + j * 1152 + nfp * 16) << 1));
                mma_f16(acco[2*nfp],     Aw, Bv[0], Bv[1]);
                mma_f16(acco[2*nfp + 1], Aw, Bv[2], Bv[3]);
            }
        }

        {
            size_t ro0 = (size_t)(bm0 + wrow + g) * SEQ + it * 64 + (r << 1);
            size_t ro1 = ro0 + (size_t)8 * SEQ;
            #pragma unroll
            for (int nf = 0; nf < 8; nf++) {
                stcs_f2(Wo + ro0 + nf * 8, acc[nf][0], acc[nf][1]);
                stcs_f2(Wo + ro1 + nf * 8, acc[nf][2], acc[nf][3]);
            }
        }
        if (it + 1 < SEQ / 64) { CPWAIT0(); __syncthreads(); }
    }

    #pragma unroll
    for (int nf = 0; nf < 8; nf++) {
        int col = nf * 8 + (r << 1);
        *(__half2*)(Cc + (size_t)(bm0 + wrow + g) * EMB + col) =
            __floats2half2_rn(acco[nf][0], acco[nf][1]);
        *(__half2*)(Cc + (size_t)(bm0 + wrow + 8 + g) * EMB + col) =
            __floats2half2_rn(acco[nf][2], acco[nf][3]);
    }
}

// ---------------- launcher --------------------------------------------------
extern "C" void kernel_launch(void* const* d_in, const int* in_sizes, int n_in,
                              void* d_out, int out_size)
{
    const float* x      = (const float*)d_in[0];
    const float* ln1_w  = (const float*)d_in[1];
    const float* ln1_b  = (const float*)d_in[2];
    const float* w_q    = (const float*)d_in[3];
    const float* w_k    = (const float*)d_in[4];
    const float* w_v    = (const float*)d_in[5];
    const float* w_o    = (const float*)d_in[6];
    const float* b_q    = (const float*)d_in[7];
    const float* b_k    = (const float*)d_in[8];
    const float* b_v    = (const float*)d_in[9];
    const float* b_o    = (const float*)d_in[10];
    const float* w_gate = (const float*)d_in[11];
    const float* b_gate = (const float*)d_in[12];
    const float* w_skip = (const float*)d_in[13];
    const float* b_skip = (const float*)d_in[14];
    const float* ln2_w  = (const float*)d_in[15];
    const float* ln2_b  = (const float*)d_in[16];
    const float* w1     = (const float*)d_in[17];
    const float* b1     = (const float*)d_in[18];
    const float* w2     = (const float*)d_in[19];
    const float* b2     = (const float*)d_in[20];

    float* out  = (float*)d_out;
    float* attw = out + (size_t)MROWS * EMB;

    __half *xnh, *qkvh, *ctxh, *hnh, *ff1h, *wcatT, *w1T, *w2T;
    float *gs, *hbuf, *bcat;
    cudaGetSymbolAddress((void**)&xnh,   g_xnh);
    cudaGetSymbolAddress((void**)&qkvh,  g_qkvh);
    cudaGetSymbolAddress((void**)&gs,    g_gs);
    cudaGetSymbolAddress((void**)&ctxh,  g_ctxh);
    cudaGetSymbolAddress((void**)&hbuf,  g_h);
    cudaGetSymbolAddress((void**)&hnh,   g_hnh);
    cudaGetSymbolAddress((void**)&ff1h,  g_ff1h);
    cudaGetSymbolAddress((void**)&wcatT, g_wcatT);
    cudaGetSymbolAddress((void**)&bcat,  g_bcat);
    cudaGetSymbolAddress((void**)&w1T,   g_w1T);
    cudaGetSymbolAddress((void**)&w2T,   g_w2T);

    cudaFuncSetAttribute(attn_fused,
                         cudaFuncAttributeMaxDynamicSharedMemorySize, ATTN_SMEM);
    cudaFuncSetAttribute(gemm_f16<2>,
                         cudaFuncAttributeMaxDynamicSharedMemorySize, GEMM_SMEM);
    cudaFuncSetAttribute(gemm_f16<4>,
                         cudaFuncAttributeMaxDynamicSharedMemorySize, GEMM_SMEM);
    cudaFuncSetAttribute(gemm64_f16<3>,
                         cudaFuncAttributeMaxDynamicSharedMemorySize, GEMM64_SMEM);
    cudaFuncSetAttribute(gemm64_f16<5>,
                         cudaFuncAttributeMaxDynamicSharedMemorySize, GEMM64_SMEM);

    prep_wcat_t<<<dim3(NCAT / 32, 768 / 32), 256>>>(
        w_q, w_k, w_v, w_gate, w_skip, w_o, wcatT);
    prep_bcat<<<(NCAT + 255) / 256, 256>>>(b_q, b_k, b_v, b_gate, b_skip, b_o, bcat);

    ln_kernel<<<MROWS, 256>>>(x, ln1_w, ln1_b, xnh);

    gemm_f16<4><<<dim3(NPROJ / 128, MROWS / 128), 128, GEMM_SMEM>>>(
        xnh, wcatT, bcat, nullptr, qkvh, gs, MROWS, NPROJ, EMB);

    attn_fused<<<dim3(SEQ / 128, NBH), 256, ATTN_SMEM>>>(qkvh, attw, ctxh);

    transpose_cvt<<<dim3(FFDIM / 32, 768 / 32), 256>>>(w1, w1T, 768, FFDIM);
    transpose_cvt<<<dim3(768 / 32, FFDIM / 32), 256>>>(w2, w2T, FFDIM, 768);

    // output projection with fused gated combine -> h
    gemm64_f16<5><<<dim3(EMB / 128, MROWS / 64), 128, GEMM64_SMEM>>>(
        ctxh, wcatT + (size_t)NPROJ * 768, bcat + NPROJ, nullptr,
        x, gs, hbuf, MROWS, EMB, EMB);

    // LN2
    ln_kernel<<<MROWS, 256>>>(hbuf, ln2_w, ln2_b, hnh);

    gemm_f16<2><<<dim3(FFDIM / 128, MROWS / 128), 128, GEMM_SMEM>>>(
        hnh, w1T, b1, nullptr, ff1h, nullptr, MROWS, FFDIM, EMB);
    gemm64_f16<3><<<dim3(EMB / 128, MROWS / 64), 128, GEMM64_SMEM>>>(
        ff1h, w2T, b2, hbuf, nullptr, nullptr, out, MROWS, EMB, FFDIM);
}

// round 17
// speedup vs baseline: 1.0452x; 1.0277x over previous
#include <cuda_runtime.h>
#include <cuda_fp16.h>
#include <math.h>

#define EMB 768
#define SEQ 2048
#define BATCH 4
#define NHEAD 12
#define HDIM 64
#define FFDIM 3072
#define MROWS (BATCH*SEQ)   // 8192
#define NPROJ 3840
#define NCAT  4608
#define NQKV  2304
#define NGS   1536
#define NBH   (BATCH*NHEAD)
#define QSCALE (0.125f * 1.44269504088896340736f)   // 1/8 * log2(e)

// ---------------- scratch (device globals) ----------------------------------
__device__ __half g_xnh  [MROWS*EMB];
__device__ __half g_qkvh [(size_t)MROWS*NQKV];
__device__ float  g_gs   [(size_t)MROWS*NGS];
__device__ __half g_ctxh [MROWS*EMB];
__device__ float  g_attno[MROWS*EMB];
__device__ float  g_h    [MROWS*EMB];
__device__ __half g_hnh  [MROWS*EMB];
__device__ __half g_ff1h [(size_t)MROWS*FFDIM];
__device__ __half g_wcatT[(size_t)NCAT*EMB];
__device__ float  g_bcat [NCAT];
__device__ __half g_w1T  [(size_t)FFDIM*EMB];
__device__ __half g_w2T  [(size_t)EMB*FFDIM];

// ---------------- helpers ----------------------------------------------------
__device__ __forceinline__ unsigned smem_u32(const void* p) {
    unsigned a;
    asm("{ .reg .u64 t; cvta.to.shared.u64 t, %1; cvt.u32.u64 %0, t; }" : "=r"(a) : "l"(p));
    return a;
}
__device__ __forceinline__ void mma_f16(float (&d)[4], const unsigned (&a)[4],
                                        unsigned b0, unsigned b1) {
    asm volatile(
        "mma.sync.aligned.m16n8k16.row.col.f32.f16.f16.f32 "
        "{%0,%1,%2,%3},{%4,%5,%6,%7},{%8,%9},{%0,%1,%2,%3};\n"
        : "+f"(d[0]), "+f"(d[1]), "+f"(d[2]), "+f"(d[3])
        : "r"(a[0]), "r"(a[1]), "r"(a[2]), "r"(a[3]), "r"(b0), "r"(b1));
}
#define LDMX4(R, addr) \
    asm volatile("ldmatrix.sync.aligned.m8n8.x4.shared.b16 {%0,%1,%2,%3}, [%4];" \
        : "=r"((R)[0]), "=r"((R)[1]), "=r"((R)[2]), "=r"((R)[3]) : "r"(addr))
#define LDMX4T(R, addr) \
    asm volatile("ldmatrix.sync.aligned.m8n8.x4.trans.shared.b16 {%0,%1,%2,%3}, [%4];" \
        : "=r"((R)[0]), "=r"((R)[1]), "=r"((R)[2]), "=r"((R)[3]) : "r"(addr))
#define CPA(dst, src) asm volatile("cp.async.cg.shared.global [%0], [%1], 16;\n" :: "r"(dst), "l"(src))
#define CPCOMMIT()    asm volatile("cp.async.commit_group;\n" ::: "memory")
#define CPWAIT0()     asm volatile("cp.async.wait_group 0;\n" ::: "memory")
#define CPWAIT1()     asm volatile("cp.async.wait_group 1;\n" ::: "memory")

__device__ __forceinline__ void stcs_f2(float* p, float a, float b) {
    asm volatile("st.global.cs.v2.f32 [%0], {%1, %2};" :: "l"(p), "f"(a), "f"(b) : "memory");
}
__device__ __forceinline__ unsigned f22h(float lo, float hi) {
    unsigned u;
    asm("cvt.rn.f16x2.f32 %0, %1, %2;" : "=r"(u) : "f"(hi), "f"(lo));
    return u;
}
__device__ __forceinline__ float gelu_exact(float v) {
    return 0.5f * v * (1.0f + erff(v * 0.70710678118654752f));
}

// ---------------- weight prep ------------------------------------------------
__global__ __launch_bounds__(256) void prep_wcat_t(
    const float* __restrict__ wq, const float* __restrict__ wk,
    const float* __restrict__ wv, const float* __restrict__ wg,
    const float* __restrict__ ws, const float* __restrict__ wo,
    __half* __restrict__ dst)
{
    __shared__ float tile[32][33];
    int bx = blockIdx.x << 5;
    int by = blockIdx.y << 5;
    int tx = threadIdx.x & 31, ty = threadIdx.x >> 5;
    int sel = bx / 768, cc0 = bx - sel * 768;
    const float* w = (sel == 0) ? wq : (sel == 1) ? wk : (sel == 2) ? wv
                   : (sel == 3) ? wg : (sel == 4) ? ws : wo;
    float sc = (sel == 0) ? QSCALE : 1.0f;
    #pragma unroll
    for (int i = 0; i < 32; i += 8)
        tile[ty + i][tx] = w[(size_t)(by + ty + i) * 768 + cc0 + tx] * sc;
    __syncthreads();
    #pragma unroll
    for (int i = 0; i < 32; i += 8)
        dst[(size_t)(bx + ty + i) * 768 + by + tx] = __float2half_rn(tile[tx][ty + i]);
}

__global__ __launch_bounds__(256) void prep_bcat(
    const float* __restrict__ bq, const float* __restrict__ bk,
    const float* __restrict__ bv, const float* __restrict__ bg,
    const float* __restrict__ bs, const float* __restrict__ bo,
    float* __restrict__ bcat)
{
    int idx = blockIdx.x * 256 + threadIdx.x;
    if (idx >= NCAT) return;
    int sel = idx / 768, cc = idx - sel * 768;
    const float* bb = (sel == 0) ? bq : (sel == 1) ? bk : (sel == 2) ? bv
                    : (sel == 3) ? bg : (sel == 4) ? bs : bo;
    bcat[idx] = bb[cc] * ((sel == 0) ? QSCALE : 1.0f);
}

__global__ __launch_bounds__(256) void transpose_cvt(
    const float* __restrict__ src, __half* __restrict__ dst, int K, int N)
{
    __shared__ float tile[32][33];
    int bx = blockIdx.x << 5, by = blockIdx.y << 5;
    int tx = threadIdx.x & 31, ty = threadIdx.x >> 5;
    #pragma unroll
    for (int i = 0; i < 32; i += 8)
        tile[ty + i][tx] = src[(size_t)(by + ty + i) * N + bx + tx];
    __syncthreads();
    #pragma unroll
    for (int i = 0; i < 32; i += 8)
        dst[(size_t)(bx + ty + i) * K + by + tx] = __float2half_rn(tile[tx][ty + i]);
}

// ---------------- layernorm → half ------------------------------------------
__global__ __launch_bounds__(256) void ln_kernel(
    const float* __restrict__ x, const float* __restrict__ w,
    const float* __restrict__ b, __half* __restrict__ y)
{
    __shared__ float sh[8];
    int t = threadIdx.x;
    const float* xr = x + (size_t)blockIdx.x * EMB;
    float2 v01 = *(const float2*)(xr + 2 * t);
    float v2 = xr[512 + t];

    float s = v01.x + v01.y + v2;
    #pragma unroll
    for (int o = 16; o; o >>= 1) s += __shfl_xor_sync(~0u, s, o);
    if ((t & 31) == 0) sh[t >> 5] = s;
    __syncthreads();
    float mean = (sh[0]+sh[1]+sh[2]+sh[3]+sh[4]+sh[5]+sh[6]+sh[7]) * (1.0f/768.0f);
    __syncthreads();

    float d0 = v01.x - mean, d1 = v01.y - mean, d2 = v2 - mean;
    float q = d0*d0 + d1*d1 + d2*d2;
    #pragma unroll
    for (int o = 16; o; o >>= 1) q += __shfl_xor_sync(~0u, q, o);
    if ((t & 31) == 0) sh[t >> 5] = q;
    __syncthreads();
    float var = (sh[0]+sh[1]+sh[2]+sh[3]+sh[4]+sh[5]+sh[6]+sh[7]) * (1.0f/768.0f);
    float rstd = rsqrtf(var + 1e-5f);

    float2 w01 = *(const float2*)(w + 2 * t);
    float2 b01 = *(const float2*)(b + 2 * t);
    __half* yr = y + (size_t)blockIdx.x * EMB;
    *(__half2*)(yr + 2 * t) =
        __floats2half2_rn(d0 * rstd * w01.x + b01.x, d1 * rstd * w01.y + b01.y);
    yr[512 + t] = __float2half_rn(d2 * rstd * w[512 + t] + b[512 + t]);
}

// ---------------- fused gated combine + LN2 ---------------------------------
__global__ __launch_bounds__(256) void combine_ln(
    const float* __restrict__ x, const float* __restrict__ gs,
    const float* __restrict__ attno, const float* __restrict__ w,
    const float* __restrict__ b, float* __restrict__ hout,
    __half* __restrict__ hn)
{
    __shared__ float sh[8];
    int t = threadIdx.x;
    size_t row = blockIdx.x;
    const float* xr = x + row * EMB;
    const float* ar = attno + row * EMB;
    const float* gsr = gs + row * NGS;

    float2 x01 = *(const float2*)(xr + 2*t);      float x2 = xr[512 + t];
    float2 a01 = *(const float2*)(ar + 2*t);      float a2 = ar[512 + t];
    float2 g01 = *(const float2*)(gsr + 2*t);     float g2 = gsr[512 + t];
    float2 s01 = *(const float2*)(gsr + 768 + 2*t); float s2 = gsr[768 + 512 + t];

    float gg0 = 1.0f / (1.0f + __expf(-g01.x));
    float gg1 = 1.0f / (1.0f + __expf(-g01.y));
    float gg2 = 1.0f / (1.0f + __expf(-g2));
    float hv0 = x01.x + gg0 * a01.x + (1.0f - gg0) * s01.x;
    float hv1 = x01.y + gg1 * a01.y + (1.0f - gg1) * s01.y;
    float hv2 = x2 + gg2 * a2 + (1.0f - gg2) * s2;

    *(float2*)(hout + row * EMB + 2*t) = make_float2(hv0, hv1);
    hout[row * EMB + 512 + t] = hv2;

    float s = hv0 + hv1 + hv2;
    #pragma unroll
    for (int o = 16; o; o >>= 1) s += __shfl_xor_sync(~0u, s, o);
    if ((t & 31) == 0) sh[t >> 5] = s;
    __syncthreads();
    float mean = (sh[0]+sh[1]+sh[2]+sh[3]+sh[4]+sh[5]+sh[6]+sh[7]) * (1.0f/768.0f);
    __syncthreads();

    float d0 = hv0-mean, d1 = hv1-mean, d2 = hv2-mean;
    float q = d0*d0 + d1*d1 + d2*d2;
    #pragma unroll
    for (int o = 16; o; o >>= 1) q += __shfl_xor_sync(~0u, q, o);
    if ((t & 31) == 0) sh[t >> 5] = q;
    __syncthreads();
    float var = (sh[0]+sh[1]+sh[2]+sh[3]+sh[4]+sh[5]+sh[6]+sh[7]) * (1.0f/768.0f);
    float rstd = rsqrtf(var + 1e-5f);

    float2 w01 = *(const float2*)(w + 2*t);
    float2 b01 = *(const float2*)(b + 2*t);
    __half* hr = hn + row * EMB;
    *(__half2*)(hr + 2*t) =
        __floats2half2_rn(d0 * rstd * w01.x + b01.x, d1 * rstd * w01.y + b01.y);
    hr[512 + t] = __float2half_rn(d2 * rstd * w[512 + t] + b[512 + t]);
}

// ---------------- fp16 GEMM 128x128x64, 4 warps, 3-stage, 2 CTA/SM ----------
// EPI: 2 bias+GELU->half; 4 split qkv/gs
#define G2_OP (128 * 72)
#define G2_STAGE (2 * G2_OP)
#define GEMM_SMEM (3 * G2_STAGE * 2)

template <int EPI>
__global__ __launch_bounds__(128, 2) void gemm_f16(
    const __half* __restrict__ A, const __half* __restrict__ Bt,
    const float* __restrict__ bias, const float* __restrict__ R,
    void* __restrict__ C0, void* __restrict__ C1, int M, int N, int K)
{
    extern __shared__ __half gsm[];
    int t = threadIdx.x, l = t & 31, warp = t >> 5;
    int wm = warp >> 1, wn = warp & 1;
    int g = l >> 2, r = l & 3;
    int bm0 = blockIdx.y * 128, bn0 = blockIdx.x * 128;
    int niter = K >> 6;

    int rowA = l & 15, colA8 = (l >> 4) << 3;
    int rowB = (l & 7) + ((l & 16) >> 1), colB8 = l & 8;
    int baseA = (wm * 64 + rowA) * 72 + colA8;
    int baseB = (wn * 64 + rowB) * 72 + colB8;

    float acc[4][8][4];
    #pragma unroll
    for (int i = 0; i < 4; i++)
        #pragma unroll
        for (int j = 0; j < 8; j++)
            #pragma unroll
            for (int q = 0; q < 4; q++) acc[i][j][q] = 0.0f;

    auto issue = [&](int it, int s) {
        int k0 = it << 6;
        unsigned sa = smem_u32(gsm + s * G2_STAGE);
        unsigned sb = sa + G2_OP * 2;
        #pragma unroll
        for (int u = 0; u < 8; u++) {
            int c = t + (u << 7);
            int row = c >> 3, cg = (c & 7) << 3;
            CPA(sa + (unsigned)((row * 72 + cg) << 1),
                A + (size_t)(bm0 + row) * K + k0 + cg);
        }
        #pragma unroll
        for (int u = 0; u < 8; u++) {
            int c = t + (u << 7);
            int row = c >> 3, cg = (c & 7) << 3;
            CPA(sb + (unsigned)((row * 72 + cg) << 1),
                Bt + (size_t)(bn0 + row) * K + k0 + cg);
        }
    };

    issue(0, 0); CPCOMMIT();
    if (niter > 1) issue(1, 1);
    CPCOMMIT();

    int st = 0;
    for (int it = 0; it < niter; ++it) {
        CPWAIT1();
        __syncthreads();
        int nx = st + 2; if (nx >= 3) nx -= 3;
        if (it + 2 < niter) issue(it + 2, nx);
        CPCOMMIT();

        unsigned sa = smem_u32(gsm + st * G2_STAGE);
        unsigned sb = sa + G2_OP * 2;
        #pragma unroll
        for (int ks = 0; ks < 4; ++ks) {
            unsigned Af[4][4], Bf[4][4];
            #pragma unroll
            for (int mf = 0; mf < 4; ++mf)
                LDMX4(Af[mf], sa + (unsigned)((baseA + mf * 1152 + ks * 16) << 1));
            #pragma unroll
            for (int nfp = 0; nfp < 4; ++nfp)
                LDMX4(Bf[nfp], sb + (unsigned)((baseB + nfp * 1152 + ks * 16) << 1));
            #pragma unroll
            for (int mf = 0; mf < 4; ++mf)
                #pragma unroll
                for (int nfp = 0; nfp < 4; ++nfp) {
                    mma_f16(acc[mf][2*nfp],   Af[mf], Bf[nfp][0], Bf[nfp][1]);
                    mma_f16(acc[mf][2*nfp+1], Af[mf], Bf[nfp][2], Bf[nfp][3]);
                }
        }
        if (++st == 3) st = 0;
    }

    #pragma unroll
    for (int mf = 0; mf < 4; ++mf) {
        #pragma unroll
        for (int nf = 0; nf < 8; ++nf) {
            int row = bm0 + wm * 64 + mf * 16 + g;
            int col = bn0 + wn * 64 + nf * 8 + (r << 1);
            float b0 = bias[col], b1 = bias[col + 1];
            float v0 = acc[mf][nf][0] + b0, v1 = acc[mf][nf][1] + b1;
            float v2 = acc[mf][nf][2] + b0, v3 = acc[mf][nf][3] + b1;
            if (EPI == 2) {
                __half* C = (__half*)C0;
                *(__half2*)(C + (size_t)row * N + col) =
                    __floats2half2_rn(gelu_exact(v0), gelu_exact(v1));
                *(__half2*)(C + (size_t)(row + 8) * N + col) =
                    __floats2half2_rn(gelu_exact(v2), gelu_exact(v3));
            } else {
                if (col < NQKV) {
                    __half* C = (__half*)C0;
                    *(__half2*)(C + (size_t)row * NQKV + col)       = __floats2half2_rn(v0, v1);
                    *(__half2*)(C + (size_t)(row + 8) * NQKV + col) = __floats2half2_rn(v2, v3);
                } else {
                    float* C = (float*)C1;
                    *(float2*)(C + (size_t)row * NGS + col - NQKV)       = make_float2(v0, v1);
                    *(float2*)(C + (size_t)(row + 8) * NGS + col - NQKV) = make_float2(v2, v3);
                }
            }
        }
    }
}

// ---------------- fp16 GEMM 64x128x64 (N=768 GEMMs) -------------------------
// EPI: 0 bias->fp32; 3 bias+R->fp32(stcs)
#define G6_A (64 * 72)
#define G6_B (128 * 72)
#define G6_STAGE (G6_A + G6_B)
#define GEMM64_SMEM (3 * G6_STAGE * 2)

template <int EPI>
__global__ __launch_bounds__(128, 2) void gemm64_f16(
    const __half* __restrict__ A, const __half* __restrict__ Bt,
    const float* __restrict__ bias, const float* __restrict__ R,
    float* __restrict__ C, int M, int N, int K)
{
    extern __shared__ __half gsm[];
    int t = threadIdx.x, l = t & 31, warp = t >> 5;
    int wm = warp >> 1, wn = warp & 1;
    int g = l >> 2, r = l & 3;
    int bm0 = blockIdx.y * 64, bn0 = blockIdx.x * 128;
    int niter = K >> 6;

    int rowA = l & 15, colA8 = (l >> 4) << 3;
    int rowB = (l & 7) + ((l & 16) >> 1), colB8 = l & 8;
    int baseA = (wm * 32 + rowA) * 72 + colA8;
    int baseB = (wn * 64 + rowB) * 72 + colB8;

    float acc[2][8][4];
    #pragma unroll
    for (int i = 0; i < 2; i++)
        #pragma unroll
        for (int j = 0; j < 8; j++)
            #pragma unroll
            for (int q = 0; q < 4; q++) acc[i][j][q] = 0.0f;

    auto issue = [&](int it, int s) {
        int k0 = it << 6;
        unsigned sa = smem_u32(gsm + s * G6_STAGE);
        unsigned sb = sa + G6_A * 2;
        #pragma unroll
        for (int u = 0; u < 4; u++) {
            int c = t + (u << 7);
            int row = c >> 3, cg = (c & 7) << 3;
            CPA(sa + (unsigned)((row * 72 + cg) << 1),
                A + (size_t)(bm0 + row) * K + k0 + cg);
        }
        #pragma unroll
        for (int u = 0; u < 8; u++) {
            int c = t + (u << 7);
            int row = c >> 3, cg = (c & 7) << 3;
            CPA(sb + (unsigned)((row * 72 + cg) << 1),
                Bt + (size_t)(bn0 + row) * K + k0 + cg);
        }
    };

    issue(0, 0); CPCOMMIT();
    if (niter > 1) issue(1, 1);
    CPCOMMIT();

    int st = 0;
    for (int it = 0; it < niter; ++it) {
        CPWAIT1();
        __syncthreads();
        int nx = st + 2; if (nx >= 3) nx -= 3;
        if (it + 2 < niter) issue(it + 2, nx);
        CPCOMMIT();

        unsigned sa = smem_u32(gsm + st * G6_STAGE);
        unsigned sb = sa + G6_A * 2;
        #pragma unroll
        for (int ks = 0; ks < 4; ++ks) {
            unsigned Af[2][4], Bf[4][4];
            #pragma unroll
            for (int mf = 0; mf < 2; ++mf)
                LDMX4(Af[mf], sa + (unsigned)((baseA + mf * 1152 + ks * 16) << 1));
            #pragma unroll
            for (int nfp = 0; nfp < 4; ++nfp)
                LDMX4(Bf[nfp], sb + (unsigned)((baseB + nfp * 1152 + ks * 16) << 1));
            #pragma unroll
            for (int mf = 0; mf < 2; ++mf)
                #pragma unroll
                for (int nfp = 0; nfp < 4; ++nfp) {
                    mma_f16(acc[mf][2*nfp],   Af[mf], Bf[nfp][0], Bf[nfp][1]);
                    mma_f16(acc[mf][2*nfp+1], Af[mf], Bf[nfp][2], Bf[nfp][3]);
                }
        }
        if (++st == 3) st = 0;
    }

    #pragma unroll
    for (int mf = 0; mf < 2; ++mf) {
        #pragma unroll
        for (int nf = 0; nf < 8; ++nf) {
            int row = bm0 + wm * 32 + mf * 16 + g;
            int col = bn0 + wn * 64 + nf * 8 + (r << 1);
            float b0 = bias[col], b1 = bias[col + 1];
            float v0 = acc[mf][nf][0] + b0, v1 = acc[mf][nf][1] + b1;
            float v2 = acc[mf][nf][2] + b0, v3 = acc[mf][nf][3] + b1;
            if (EPI == 0) {
                *(float2*)(C + (size_t)row * N + col)       = make_float2(v0, v1);
                *(float2*)(C + (size_t)(row + 8) * N + col) = make_float2(v2, v3);
            } else {
                const float2 r0 = *(const float2*)(R + (size_t)row * N + col);
                const float2 r1 = *(const float2*)(R + (size_t)(row + 8) * N + col);
                stcs_f2(C + (size_t)row * N + col,       v0 + r0.x, v1 + r0.y);
                stcs_f2(C + (size_t)(row + 8) * N + col, v2 + r1.x, v3 + r1.y);
            }
        }
    }
}

// ---------------- fused flash-style attention (fp16, 2-stage, exp2) ---------
#define ATTN_SMEM ((128*72 + 4*64*72) * 2)

__global__ __launch_bounds__(256, 2) void attn_fused(
    const __half* __restrict__ qkv, float* __restrict__ attw,
    __half* __restrict__ ctx)
{
    extern __shared__ __half smh[];
    __half* Qs  = smh;
    __half* Ks0 = Qs  + 128 * 72;
    __half* Ks1 = Ks0 + 64 * 72;
    __half* Vs0 = Ks1 + 64 * 72;
    __half* Vs1 = Vs0 + 64 * 72;

    int bh = blockIdx.y, b = bh / NHEAD, h = bh % NHEAD;
    const __half* Qp = qkv + (size_t)b * SEQ * NQKV + h * HDIM;
    const __half* Kp = Qp + 768;
    const __half* Vp = Qp + 1536;
    float* Wo = attw + (size_t)bh * SEQ * SEQ;
    __half* Cc = ctx + (size_t)b * SEQ * EMB + h * HDIM;

    int t = threadIdx.x, l = t & 31, warp = t >> 5;
    int g = l >> 2, r = l & 3;
    int wrow = warp * 16;
    int bm0 = blockIdx.x * 128;

    unsigned sq  = smem_u32(Qs);
    unsigned sk0 = smem_u32(Ks0), sk1 = smem_u32(Ks1);
    unsigned sv0 = smem_u32(Vs0), sv1 = smem_u32(Vs1);

    int rowA = l & 15, colA8 = (l >> 4) << 3;
    int rowB = (l & 7) + ((l & 16) >> 1), colB8 = l & 8;
    int baseQA = (wrow + rowA) * 72 + colA8;
    int baseKB = rowB * 72 + colB8;
    int baseVB = rowA * 72 + colA8;

    auto issueK = [&](int it, int s) {
        unsigned sk = s ? sk1 : sk0;
        #pragma unroll
        for (int u = 0; u < 2; u++) {
            int c = t + (u << 8);
            int row = c >> 3, cc8 = (c & 7) << 3;
            CPA(sk + (unsigned)((row * 72 + cc8) << 1),
                Kp + (size_t)(it * 64 + row) * NQKV + cc8);
        }
    };
    auto issueV = [&](int it, int s) {
        unsigned sv = s ? sv1 : sv0;
        #pragma unroll
        for (int u = 0; u < 2; u++) {
            int c = t + (u << 8);
            int row = c >> 3, cc8 = (c & 7) << 3;
            CPA(sv + (unsigned)((row * 72 + cc8) << 1),
                Vp + (size_t)(it * 64 + row) * NQKV + cc8);
        }
    };

    {
        #pragma unroll
        for (int u = 0; u < 4; u++) {
            int c = t + (u << 8);
            int row = c >> 3, cc8 = (c & 7) << 3;
            CPA(sq + (unsigned)((row * 72 + cc8) << 1),
                Qp + (size_t)(bm0 + row) * NQKV + cc8);
        }
    }
    issueK(0, 0); CPCOMMIT();
    CPWAIT0(); __syncthreads();

    unsigned QA[4][4];
    #pragma unroll
    for (int ks = 0; ks < 4; ++ks)
        LDMX4(QA[ks], sq + (unsigned)((baseQA + ks * 16) << 1));

    float mh[2] = {-1e30f, -1e30f};
    float lh[2] = {0.0f, 0.0f};

    // ---------------- pass 1: online stats (base-2 domain) -------------------
    for (int it = 0; it < SEQ / 64; ++it) {
        if (it + 1 < SEQ / 64) { issueK(it + 1, (it + 1) & 1); CPCOMMIT(); }
        unsigned sk = (it & 1) ? sk1 : sk0;

        float acc[8][4];
        #pragma unroll
        for (int nf = 0; nf < 8; nf++)
            #pragma unroll
            for (int q = 0; q < 4; q++) acc[nf][q] = 0.0f;

        #pragma unroll
        for (int ks = 0; ks < 4; ks++) {
            #pragma unroll
            for (int nfp = 0; nfp < 4; nfp++) {
                unsigned Bq[4];
                LDMX4(Bq, sk + (unsigned)((baseKB + nfp * 1152 + ks * 16) << 1));
                mma_f16(acc[2*nfp],     QA[ks], Bq[0], Bq[1]);
                mma_f16(acc[2*nfp + 1], QA[ks], Bq[2], Bq[3]);
            }
        }

        #pragma unroll
        for (int half = 0; half < 2; half++) {
            float mb = -1e30f;
            #pragma unroll
            for (int nf = 0; nf < 8; nf++)
                mb = fmaxf(mb, fmaxf(acc[nf][2*half], acc[nf][2*half+1]));
            mb = fmaxf(mb, __shfl_xor_sync(~0u, mb, 1));
            mb = fmaxf(mb, __shfl_xor_sync(~0u, mb, 2));
            float mn = fmaxf(mh[half], mb);
            float ss = 0.0f;
            #pragma unroll
            for (int nf = 0; nf < 8; nf++)
                ss += exp2f(acc[nf][2*half] - mn) + exp2f(acc[nf][2*half+1] - mn);
            ss += __shfl_xor_sync(~0u, ss, 1);
            ss += __shfl_xor_sync(~0u, ss, 2);
            lh[half] = lh[half] * exp2f(mh[half] - mn) + ss;
            mh[half] = mn;
        }
        if (it + 1 < SEQ / 64) { CPWAIT0(); __syncthreads(); }
    }

    float invl[2] = {1.0f / lh[0], 1.0f / lh[1]};

    float acco[8][4];
    #pragma unroll
    for (int nf = 0; nf < 8; nf++)
        #pragma unroll
        for (int q = 0; q < 4; q++) acco[nf][q] = 0.0f;

    __syncthreads();
    issueK(0, 0); issueV(0, 0); CPCOMMIT();
    CPWAIT0(); __syncthreads();

    // ---------------- pass 2: recompute, PV first, store last ---------------
    for (int it = 0; it < SEQ / 64; ++it) {
        if (it + 1 < SEQ / 64) {
            issueK(it + 1, (it + 1) & 1); issueV(it + 1, (it + 1) & 1); CPCOMMIT();
        }
        unsigned sk = (it & 1) ? sk1 : sk0;
        unsigned sv = (it & 1) ? sv1 : sv0;

        float acc[8][4];
        #pragma unroll
        for (int nf = 0; nf < 8; nf++)
            #pragma unroll
            for (int q = 0; q < 4; q++) acc[nf][q] = 0.0f;

        #pragma unroll
        for (int ks = 0; ks < 4; ks++) {
            #pragma unroll
            for (int nfp = 0; nfp < 4; nfp++) {
                unsigned Bq[4];
                LDMX4(Bq, sk + (unsigned)((baseKB + nfp * 1152 + ks * 16) << 1));
                mma_f16(acc[2*nfp],     QA[ks], Bq[0], Bq[1]);
                mma_f16(acc[2*nfp + 1], QA[ks], Bq[2], Bq[3]);
            }
        }

        #pragma unroll
        for (int nf = 0; nf < 8; nf++) {
            acc[nf][0] = exp2f(acc[nf][0] - mh[0]) * invl[0];
            acc[nf][1] = exp2f(acc[nf][1] - mh[0]) * invl[0];
            acc[nf][2] = exp2f(acc[nf][2] - mh[1]) * invl[1];
            acc[nf][3] = exp2f(acc[nf][3] - mh[1]) * invl[1];
        }

        #pragma unroll
        for (int j = 0; j < 4; j++) {
            unsigned Aw[4];
            Aw[0] = f22h(acc[2*j][0],   acc[2*j][1]);
            Aw[1] = f22h(acc[2*j][2],   acc[2*j][3]);
            Aw[2] = f22h(acc[2*j+1][0], acc[2*j+1][1]);
            Aw[3] = f22h(acc[2*j+1][2], acc[2*j+1][3]);
            #pragma unroll
            for (int nfp = 0; nfp < 4; nfp++) {
                unsigned Bv[4];
                LDMX4T(Bv, sv + (unsigned)((baseVB + j * 1152 + nfp * 16) << 1));
                mma_f16(acco[2*nfp],     Aw, Bv[0], Bv[1]);
                mma_f16(acco[2*nfp + 1], Aw, Bv[2], Bv[3]);
            }
        }

        {
            size_t ro0 = (size_t)(bm0 + wrow + g) * SEQ + it * 64 + (r << 1);
            size_t ro1 = ro0 + (size_t)8 * SEQ;
            #pragma unroll
            for (int nf = 0; nf < 8; nf++) {
                stcs_f2(Wo + ro0 + nf * 8, acc[nf][0], acc[nf][1]);
                stcs_f2(Wo + ro1 + nf * 8, acc[nf][2], acc[nf][3]);
            }
        }
        if (it + 1 < SEQ / 64) { CPWAIT0(); __syncthreads(); }
    }

    #pragma unroll
    for (int nf = 0; nf < 8; nf++) {
        int col = nf * 8 + (r << 1);
        *(__half2*)(Cc + (size_t)(bm0 + wrow + g) * EMB + col) =
            __floats2half2_rn(acco[nf][0], acco[nf][1]);
        *(__half2*)(Cc + (size_t)(bm0 + wrow + 8 + g) * EMB + col) =
            __floats2half2_rn(acco[nf][2], acco[nf][3]);
    }
}

// ---------------- launcher --------------------------------------------------
extern "C" void kernel_launch(void* const* d_in, const int* in_sizes, int n_in,
                              void* d_out, int out_size)
{
    const float* x      = (const float*)d_in[0];
    const float* ln1_w  = (const float*)d_in[1];
    const float* ln1_b  = (const float*)d_in[2];
    const float* w_q    = (const float*)d_in[3];
    const float* w_k    = (const float*)d_in[4];
    const float* w_v    = (const float*)d_in[5];
    const float* w_o    = (const float*)d_in[6];
    const float* b_q    = (const float*)d_in[7];
    const float* b_k    = (const float*)d_in[8];
    const float* b_v    = (const float*)d_in[9];
    const float* b_o    = (const float*)d_in[10];
    const float* w_gate = (const float*)d_in[11];
    const float* b_gate = (const float*)d_in[12];
    const float* w_skip = (const float*)d_in[13];
    const float* b_skip = (const float*)d_in[14];
    const float* ln2_w  = (const float*)d_in[15];
    const float* ln2_b  = (const float*)d_in[16];
    const float* w1     = (const float*)d_in[17];
    const float* b1     = (const float*)d_in[18];
    const float* w2     = (const float*)d_in[19];
    const float* b2     = (const float*)d_in[20];

    float* out  = (float*)d_out;
    float* attw = out + (size_t)MROWS * EMB;

    __half *xnh, *qkvh, *ctxh, *hnh, *ff1h, *wcatT, *w1T, *w2T;
    float *gs, *attno, *hbuf, *bcat;
    cudaGetSymbolAddress((void**)&xnh,   g_xnh);
    cudaGetSymbolAddress((void**)&qkvh,  g_qkvh);
    cudaGetSymbolAddress((void**)&gs,    g_gs);
    cudaGetSymbolAddress((void**)&ctxh,  g_ctxh);
    cudaGetSymbolAddress((void**)&attno, g_attno);
    cudaGetSymbolAddress((void**)&hbuf,  g_h);
    cudaGetSymbolAddress((void**)&hnh,   g_hnh);
    cudaGetSymbolAddress((void**)&ff1h,  g_ff1h);
    cudaGetSymbolAddress((void**)&wcatT, g_wcatT);
    cudaGetSymbolAddress((void**)&bcat,  g_bcat);
    cudaGetSymbolAddress((void**)&w1T,   g_w1T);
    cudaGetSymbolAddress((void**)&w2T,   g_w2T);

    cudaFuncSetAttribute(attn_fused,
                         cudaFuncAttributeMaxDynamicSharedMemorySize, ATTN_SMEM);
    cudaFuncSetAttribute(gemm_f16<2>,
                         cudaFuncAttributeMaxDynamicSharedMemorySize, GEMM_SMEM);
    cudaFuncSetAttribute(gemm_f16<4>,
                         cudaFuncAttributeMaxDynamicSharedMemorySize, GEMM_SMEM);
    cudaFuncSetAttribute(gemm64_f16<0>,
                         cudaFuncAttributeMaxDynamicSharedMemorySize, GEMM64_SMEM);
    cudaFuncSetAttribute(gemm64_f16<3>,
                         cudaFuncAttributeMaxDynamicSharedMemorySize, GEMM64_SMEM);

    prep_wcat_t<<<dim3(NCAT / 32, 768 / 32), 256>>>(
        w_q, w_k, w_v, w_gate, w_skip, w_o, wcatT);
    prep_bcat<<<(NCAT + 255) / 256, 256>>>(b_q, b_k, b_v, b_gate, b_skip, b_o, bcat);

    ln_kernel<<<MROWS, 256>>>(x, ln1_w, ln1_b, xnh);

    gemm_f16<4><<<dim3(NPROJ / 128, MROWS / 128), 128, GEMM_SMEM>>>(
        xnh, wcatT, bcat, nullptr, qkvh, gs, MROWS, NPROJ, EMB);

    attn_fused<<<dim3(SEQ / 128, NBH), 256, ATTN_SMEM>>>(qkvh, attw, ctxh);

    transpose_cvt<<<dim3(FFDIM / 32, 768 / 32), 256>>>(w1, w1T, 768, FFDIM);
    transpose_cvt<<<dim3(768 / 32, FFDIM / 32), 256>>>(w2, w2T, FFDIM, 768);

    // output projection (64-row tiles)
    gemm64_f16<0><<<dim3(EMB / 128, MROWS / 64), 128, GEMM64_SMEM>>>(
        ctxh, wcatT + (size_t)NPROJ * 768, bcat + NPROJ, nullptr,
        attno, MROWS, EMB, EMB);

    combine_ln<<<MROWS, 256>>>(x, gs, attno, ln2_w, ln2_b, hbuf, hnh);

    gemm_f16<2><<<dim3(FFDIM / 128, MROWS / 128), 128, GEMM_SMEM>>>(
        hnh, w1T, b1, nullptr, ff1h, nullptr, MROWS, FFDIM, EMB);
    gemm64_f16<3><<<dim3(EMB / 128, MROWS / 64), 128, GEMM64_SMEM>>>(
        ff1h, w2T, b2, hbuf, out, MROWS, EMB, FFDIM);
}